// round 6
// baseline (speedup 1.0000x reference)
#include <cuda_runtime.h>
#include <cuda_fp16.h>
#include <cstdint>

// Problem dimensions (fixed by the dataset)
#define CN 20000
#define CE 160000
#define CP 10000
#define CD 512
#define CS 128
#define CH 1024
#define K1 (2*CD+CS)   // 1152

#define CN_PAD 20096   // 157 * 128
#define CP_PAD 10112   // 79 * 128

// ---------------------------------------------------------------------------
// Static device scratch (no allocations allowed)
// ---------------------------------------------------------------------------
__device__ __half g_a1hi[(size_t)CE * K1];      // GEMM1 A pre-split
__device__ __half g_a1lo[(size_t)CE * K1];
__device__ __half g_hidhi[(size_t)CE * CH];     // relu(h@We1+be1) hi/lo
__device__ __half g_hidlo[(size_t)CE * CH];
__device__ __half g_anhi[(size_t)CN_PAD * CH];  // node GEMM A pre-split
__device__ __half g_anlo[(size_t)CN_PAD * CH];
__device__ __half g_aphi[(size_t)CP_PAD * K1];  // pred GEMM A pre-split
__device__ __half g_aplo[(size_t)CP_PAD * K1];
__device__ __half g_w1hi[(size_t)CH * K1];      // We1^T
__device__ __half g_w1lo[(size_t)CH * K1];
__device__ __half g_w2hi[(size_t)CD * CH];      // We2^T
__device__ __half g_w2lo[(size_t)CD * CH];
__device__ __half g_wnhi[(size_t)CD * CH];      // Wn^T
__device__ __half g_wnlo[(size_t)CD * CH];
__device__ __half g_wphi[(size_t)CD * K1];      // Wp1^T
__device__ __half g_wplo[(size_t)CD * K1];
__device__ float g_ef[(size_t)CE * CD];         // e_f  [E,512]
__device__ float g_a[CE];
__device__ float g_ex[CE];
__device__ float g_m[CN];
__device__ float g_den[CN];
__device__ float g_zf[(size_t)CN * CD];
__device__ float g_newn[(size_t)CN * CD];
__device__ float g_ph[(size_t)CP * CD];

// ---------------------------------------------------------------------------
// PTX helpers (all sm_80-class: assemble on plain sm_100)
// ---------------------------------------------------------------------------
__device__ __forceinline__ uint32_t smem_u32(const void* p) {
    uint32_t a;
    asm("{ .reg .u64 t; cvta.to.shared.u64 t, %1; cvt.u32.u64 %0, t; }" : "=r"(a) : "l"(p));
    return a;
}
__device__ __forceinline__ void ldsm_x4(uint32_t* r, uint32_t addr) {
    asm volatile("ldmatrix.sync.aligned.m8n8.x4.shared.b16 {%0,%1,%2,%3}, [%4];"
                 : "=r"(r[0]), "=r"(r[1]), "=r"(r[2]), "=r"(r[3]) : "r"(addr));
}
__device__ __forceinline__ void mma16816(float* d, const uint32_t* a,
                                         const uint32_t b0, const uint32_t b1) {
    asm volatile(
        "mma.sync.aligned.m16n8k16.row.col.f32.f16.f16.f32 "
        "{%0,%1,%2,%3}, {%4,%5,%6,%7}, {%8,%9}, {%0,%1,%2,%3};"
        : "+f"(d[0]), "+f"(d[1]), "+f"(d[2]), "+f"(d[3])
        : "r"(a[0]), "r"(a[1]), "r"(a[2]), "r"(a[3]), "r"(b0), "r"(b1));
}
__device__ __forceinline__ void cp16(uint32_t dst, const void* src) {
    asm volatile("cp.async.cg.shared.global [%0], [%1], 16;"
                 :: "r"(dst), "l"(__cvta_generic_to_global(src)) : "memory");
}
#define CP_COMMIT() asm volatile("cp.async.commit_group;" ::: "memory")
#define CP_WAIT1()  asm volatile("cp.async.wait_group 1;" ::: "memory")

__device__ __forceinline__ uint32_t packh(__half a, __half b) {
    return (uint32_t)__half_as_ushort(a) | ((uint32_t)__half_as_ushort(b) << 16);
}
__device__ __forceinline__ void splitH2(float x0, float x1, uint32_t& hi, uint32_t& lo) {
    __half h0 = __float2half_rn(x0);
    __half h1 = __float2half_rn(x1);
    float r0 = x0 - __half2float(h0);
    float r1 = x1 - __half2float(h1);
    hi = packh(h0, h1);
    lo = packh(__float2half_rn(r0), __float2half_rn(r1));
}

// ---------------------------------------------------------------------------
// Split-fp16 3-pass tensor GEMM.  C[M,Ntot] = act(A @ B^T + bias)
// A: pre-split fp16 hi/lo [Mpad][Ktot] row-major; B: pre-split [Ntot][Ktot].
// CTA: 128 threads, 4 warps (2m x 2n), CTA tile 128x128, warp tile 64x64,
// BK=32, 3-stage cp.async pipeline, XOR-swizzled 64B smem rows.
// OUTH: write fp16 hi/lo pair (with relu). else fp32 (+optional relu).
// ---------------------------------------------------------------------------
#define MATB   8192u                    // 128 rows x 64B
#define STAGEB 32768u                   // Ah Al Bh Bl
#define SMEM_MMA (3 * STAGEB)           // 96 KB

template <bool OUTH, bool RELU>
__global__ void __launch_bounds__(128, 2)
mma_gemm(int M, int Ntot, int Ktot,
         const __half* __restrict__ Ahi, const __half* __restrict__ Alo,
         const __half* __restrict__ Bhi, const __half* __restrict__ Blo,
         const float* __restrict__ bias,
         __half* __restrict__ outHi, __half* __restrict__ outLo,
         float* __restrict__ outF)
{
    extern __shared__ char smem[];
    const uint32_t sb = smem_u32(smem);
    const int tid  = threadIdx.x;
    const int wid  = tid >> 5, lane = tid & 31;
    const int warpM = wid & 1, warpN = wid >> 1;
    const int rowBase = blockIdx.y * 128;
    const int colBase = blockIdx.x * 128;

    // per-thread load geometry: one row per thread, 4 swizzled 16B chunks/matrix
    const int lr = tid;                        // 0..127
    const uint32_t lxor = ((uint32_t)(lr >> 1) & 3);
    const size_t aRow = (size_t)(rowBase + lr) * Ktot;
    const size_t bRow = (size_t)(colBase + lr) * Ktot;

    auto loadStage = [&](int st, int c) {
        const int k0 = c << 5;
        const uint32_t base = sb + (uint32_t)st * STAGEB + (uint32_t)lr * 64u;
#pragma unroll
        for (int q = 0; q < 4; q++) {
            const uint32_t d = ((uint32_t)q ^ lxor) * 16u;
            cp16(base +             d, Ahi + aRow + k0 + q * 8);
            cp16(base + MATB      + d, Alo + aRow + k0 + q * 8);
            cp16(base + 2 * MATB  + d, Bhi + bRow + k0 + q * 8);
            cp16(base + 3 * MATB  + d, Blo + bRow + k0 + q * 8);
        }
    };

    float acc[4][8][4];
#pragma unroll
    for (int a = 0; a < 4; a++)
#pragma unroll
        for (int b = 0; b < 8; b++)
#pragma unroll
            for (int c = 0; c < 4; c++) acc[a][b][c] = 0.f;

    const int NCH = Ktot >> 5;

    // prologue: stages 0,1 <- chunks 0,1
    loadStage(0, 0); CP_COMMIT();
    loadStage(1, 1); CP_COMMIT();

    // per-lane ldsm address components (swizzle folds to lane-only term since
    // all tile row-bases are multiples of 16)
    const uint32_t xl = ((uint32_t)lane >> 1) & 3u;
    uint32_t lsel[2];
#pragma unroll
    for (int s = 0; s < 2; s++)
        lsel[s] = (uint32_t)(lane & 15) * 64u +
                  ((((uint32_t)s * 2u + ((uint32_t)lane >> 4)) ^ xl) * 16u);

    for (int c = 0; c < NCH; c++) {
        CP_WAIT1();
        __syncthreads();
        if (c + 2 < NCH) loadStage((c + 2) % 3, c + 2);
        CP_COMMIT();   // always: keeps group accounting uniform

        const uint32_t stb = sb + (uint32_t)(c % 3) * STAGEB;
        const uint32_t aH = stb, aL = stb + MATB, bH = stb + 2 * MATB, bL = stb + 3 * MATB;

#pragma unroll
        for (int s = 0; s < 2; s++) {
            uint32_t ah[4][4], al[4][4], bh[4][4], bl[4][4];
#pragma unroll
            for (int mt = 0; mt < 4; mt++) {
                const uint32_t ro = (uint32_t)(warpM * 64 + mt * 16) * 64u + lsel[s];
                ldsm_x4(ah[mt], aH + ro);
                ldsm_x4(al[mt], aL + ro);
            }
#pragma unroll
            for (int i = 0; i < 4; i++) {
                const uint32_t ro = (uint32_t)(warpN * 64 + i * 16) * 64u + lsel[s];
                ldsm_x4(bh[i], bH + ro);
                ldsm_x4(bl[i], bL + ro);
            }
            // pass-major: long reuse distance on each accumulator
#pragma unroll
            for (int mt = 0; mt < 4; mt++)
#pragma unroll
                for (int nt = 0; nt < 8; nt++)
                    mma16816(acc[mt][nt], ah[mt], bh[nt >> 1][nt & 1], bh[nt >> 1][2 + (nt & 1)]);
#pragma unroll
            for (int mt = 0; mt < 4; mt++)
#pragma unroll
                for (int nt = 0; nt < 8; nt++)
                    mma16816(acc[mt][nt], ah[mt], bl[nt >> 1][nt & 1], bl[nt >> 1][2 + (nt & 1)]);
#pragma unroll
            for (int mt = 0; mt < 4; mt++)
#pragma unroll
                for (int nt = 0; nt < 8; nt++)
                    mma16816(acc[mt][nt], al[mt], bh[nt >> 1][nt & 1], bh[nt >> 1][2 + (nt & 1)]);
        }
    }

    // epilogue: c0/c1 -> row (lane>>2), c2/c3 -> +8; cols 2*(lane&3)+{0,1}
#pragma unroll
    for (int mt = 0; mt < 4; mt++) {
        const int r0 = rowBase + warpM * 64 + mt * 16 + (lane >> 2);
#pragma unroll
        for (int nt = 0; nt < 8; nt++) {
            const int c0 = colBase + warpN * 64 + nt * 8 + (lane & 3) * 2;
            const float b0 = bias[c0], b1 = bias[c0 + 1];
            float v00 = acc[mt][nt][0] + b0, v01 = acc[mt][nt][1] + b1;
            float v10 = acc[mt][nt][2] + b0, v11 = acc[mt][nt][3] + b1;
            if (RELU) {
                v00 = fmaxf(v00, 0.f); v01 = fmaxf(v01, 0.f);
                v10 = fmaxf(v10, 0.f); v11 = fmaxf(v11, 0.f);
            }
            if (OUTH) {
                uint32_t h, l;
                if (r0 < M) {
                    splitH2(v00, v01, h, l);
                    *(uint32_t*)(outHi + (size_t)r0 * Ntot + c0) = h;
                    *(uint32_t*)(outLo + (size_t)r0 * Ntot + c0) = l;
                }
                if (r0 + 8 < M) {
                    splitH2(v10, v11, h, l);
                    *(uint32_t*)(outHi + (size_t)(r0 + 8) * Ntot + c0) = h;
                    *(uint32_t*)(outLo + (size_t)(r0 + 8) * Ntot + c0) = l;
                }
            } else {
                if (r0 < M)
                    *(float2*)(outF + (size_t)r0 * Ntot + c0) = make_float2(v00, v01);
                if (r0 + 8 < M)
                    *(float2*)(outF + (size_t)(r0 + 8) * Ntot + c0) = make_float2(v10, v11);
            }
        }
    }
}

// ---------------------------------------------------------------------------
// A-operand prep kernels: gather + fp32 -> fp16 hi/lo split
// ---------------------------------------------------------------------------
__global__ void split_gather_edge(const float* __restrict__ nf, const float* __restrict__ sf,
                                  const int* __restrict__ src, const int* __restrict__ dst,
                                  __half* __restrict__ hi, __half* __restrict__ lo)
{
    const int e = blockIdx.x;
    const int j = threadIdx.x * 4;          // 288 threads -> 1152
    const float* p;
    if (j < CD)            p = nf + (size_t)src[e] * CD + j;
    else if (j < CD + CS)  p = sf + (size_t)e * CS + (j - CD);
    else                   p = nf + (size_t)dst[e] * CD + (j - CD - CS);
    float4 v = *(const float4*)p;
    uint32_t h0, l0, h1, l1;
    splitH2(v.x, v.y, h0, l0);
    splitH2(v.z, v.w, h1, l1);
    size_t o = (size_t)e * K1 + j;
    *(uint2*)(hi + o) = make_uint2(h0, h1);
    *(uint2*)(lo + o) = make_uint2(l0, l1);
}

__global__ void split_node(const float* __restrict__ nf, const float* __restrict__ zf,
                           __half* __restrict__ hi, __half* __restrict__ lo)
{
    const int r = blockIdx.x;                  // 0..CN_PAD-1
    const int rs = r < CN ? r : CN - 1;
    const int j = threadIdx.x * 4;             // 256 threads -> 1024
    const float* p = (j < CD) ? (nf + (size_t)rs * CD + j)
                              : (zf + (size_t)rs * CD + (j - CD));
    float4 v = *(const float4*)p;
    uint32_t h0, l0, h1, l1;
    splitH2(v.x, v.y, h0, l0);
    splitH2(v.z, v.w, h1, l1);
    size_t o = (size_t)r * CH + j;
    *(uint2*)(hi + o) = make_uint2(h0, h1);
    *(uint2*)(lo + o) = make_uint2(l0, l1);
}

__global__ void split_pred(const float* __restrict__ newn, const float* __restrict__ sf,
                           const int* __restrict__ src, const int* __restrict__ dst,
                           const int* __restrict__ pidx,
                           __half* __restrict__ hi, __half* __restrict__ lo)
{
    const int r = blockIdx.x;                  // 0..CP_PAD-1
    const int rp = r < CP ? r : CP - 1;
    const int pe = pidx[rp];
    const int j = threadIdx.x * 4;             // 288 threads -> 1152
    const float* p;
    if (j < CD)            p = newn + (size_t)src[pe] * CD + j;
    else if (j < CD + CS)  p = sf + (size_t)pe * CS + (j - CD);
    else                   p = newn + (size_t)dst[pe] * CD + (j - CD - CS);
    float4 v = *(const float4*)p;
    uint32_t h0, l0, h1, l1;
    splitH2(v.x, v.y, h0, l0);
    splitH2(v.z, v.w, h1, l1);
    size_t o = (size_t)r * K1 + j;
    *(uint2*)(hi + o) = make_uint2(h0, h1);
    *(uint2*)(lo + o) = make_uint2(l0, l1);
}

// Weight prep: W[K][N] fp32 -> Wt hi/lo [N][K] fp16 (tiled transpose)
__global__ void transpose_split(const float* __restrict__ W,
                                __half* __restrict__ hi,
                                __half* __restrict__ lo,
                                int K, int N)
{
    __shared__ float t[32][33];
    const int nb = blockIdx.x * 32, kb = blockIdx.y * 32;
    const int x = threadIdx.x, y = threadIdx.y;   // (32,8)
#pragma unroll
    for (int i = 0; i < 32; i += 8)
        t[y + i][x] = W[(size_t)(kb + y + i) * N + nb + x];
    __syncthreads();
#pragma unroll
    for (int i = 0; i < 32; i += 8) {
        float v = t[x][y + i];
        __half h = __float2half_rn(v);
        size_t o = (size_t)(nb + y + i) * K + kb + x;
        hi[o] = h;
        lo[o] = __float2half_rn(v - __half2float(h));
    }
}

// ---------------------------------------------------------------------------
// Segment softmax + scatter
// ---------------------------------------------------------------------------
__device__ __forceinline__ void atomicMaxFloat(float* addr, float value) {
    if (value >= 0.f)
        atomicMax((int*)addr, __float_as_int(value));
    else
        atomicMin((unsigned int*)addr, __float_as_uint(value));
}

__global__ void init_kernel(float* __restrict__ m, float* __restrict__ den,
                            float* __restrict__ zf)
{
    size_t i = (size_t)blockIdx.x * 256 + threadIdx.x;
    if (i < (size_t)CN * CD) zf[i] = 0.f;
    if (i < CN) { m[i] = __int_as_float(0xff800000); den[i] = 0.f; }
}

__global__ void edge_logit_kernel(const float* __restrict__ ef,
                                  const float* __restrict__ Wa,
                                  const float* __restrict__ ba,
                                  const int*   __restrict__ dst,
                                  float* __restrict__ a,
                                  float* __restrict__ m)
{
    int e    = blockIdx.x * 8 + (threadIdx.x >> 5);
    int lane = threadIdx.x & 31;
    if (e >= CE) return;
    const float4* row = (const float4*)(ef + (size_t)e * CD);
    const float4* w   = (const float4*)Wa;
    float s = 0.f;
#pragma unroll
    for (int i = 0; i < 4; i++) {
        float4 v  = row[lane + i * 32];
        float4 wv = w[lane + i * 32];
        s += v.x * wv.x + v.y * wv.y + v.z * wv.z + v.w * wv.w;
    }
#pragma unroll
    for (int o = 16; o; o >>= 1) s += __shfl_xor_sync(0xffffffffu, s, o);
    if (lane == 0) {
        s += ba[0];
        a[e] = s;
        atomicMaxFloat(&m[dst[e]], s);
    }
}

__global__ void edge_exp_kernel(const float* __restrict__ a,
                                const int*   __restrict__ dst,
                                const float* __restrict__ m,
                                float* __restrict__ ex,
                                float* __restrict__ den)
{
    int e = blockIdx.x * 256 + threadIdx.x;
    if (e >= CE) return;
    int d = dst[e];
    float v = expf(a[e] - m[d]);
    ex[e] = v;
    atomicAdd(&den[d], v);
}

__global__ void scatter_z_kernel(const float* __restrict__ nf,
                                 const float* __restrict__ ef,
                                 const int*   __restrict__ src,
                                 const int*   __restrict__ dst,
                                 const float* __restrict__ ex,
                                 const float* __restrict__ den,
                                 float* __restrict__ zf)
{
    int e = blockIdx.x;
    int t = threadIdx.x;
    int d = dst[e], s = src[e];
    float alpha = ex[e] / den[d];
    float4 v = *(const float4*)(nf + (size_t)s * CD + t * 4);
    float4 w = *(const float4*)(ef + (size_t)e * CD + t * 4);
    float* zp = zf + (size_t)d * CD + t * 4;
    atomicAdd(zp + 0, alpha * (v.x + w.x));
    atomicAdd(zp + 1, alpha * (v.y + w.y));
    atomicAdd(zp + 2, alpha * (v.z + w.z));
    atomicAdd(zp + 3, alpha * (v.w + w.w));
}

__global__ void pred_kernel(const float* __restrict__ ph,
                            const float* __restrict__ Wp2,
                            const float* __restrict__ bp2,
                            float* __restrict__ out)
{
    int p    = blockIdx.x * 8 + (threadIdx.x >> 5);
    int lane = threadIdx.x & 31;
    if (p >= CP) return;
    const float4* row = (const float4*)(ph + (size_t)p * CD);
    const float4* w   = (const float4*)Wp2;
    float s = 0.f;
#pragma unroll
    for (int i = 0; i < 4; i++) {
        float4 v  = row[lane + i * 32];
        float4 wv = w[lane + i * 32];
        s += v.x * wv.x + v.y * wv.y + v.z * wv.z + v.w * wv.w;
    }
#pragma unroll
    for (int o = 16; o; o >>= 1) s += __shfl_xor_sync(0xffffffffu, s, o);
    if (lane == 0) out[p] = s + bp2[0];
}

// ---------------------------------------------------------------------------
// Launch
// ---------------------------------------------------------------------------
extern "C" void kernel_launch(void* const* d_in, const int* in_sizes, int n_in,
                              void* d_out, int out_size)
{
    const float* n_f  = (const float*)d_in[0];
    const float* s_f  = (const float*)d_in[1];
    const float* We1  = (const float*)d_in[2];
    const float* be1  = (const float*)d_in[3];
    const float* We2  = (const float*)d_in[4];
    const float* be2  = (const float*)d_in[5];
    const float* Wa   = (const float*)d_in[6];
    const float* ba   = (const float*)d_in[7];
    const float* Wn   = (const float*)d_in[8];
    const float* bn   = (const float*)d_in[9];
    const float* Wp1  = (const float*)d_in[10];
    const float* bp1  = (const float*)d_in[11];
    const float* Wp2  = (const float*)d_in[12];
    const float* bp2  = (const float*)d_in[13];
    const int*   src  = (const int*)d_in[14];
    const int*   dst  = (const int*)d_in[15];
    const int*   pidx = (const int*)d_in[16];
    float* out = (float*)d_out;

    __half *a1hi, *a1lo, *hidHi, *hidLo, *anhi, *anlo, *aphi, *aplo;
    __half *w1hi, *w1lo, *w2hi, *w2lo, *wnhi, *wnlo, *wphi, *wplo;
    float *efP, *aP, *exP, *mP, *denP, *zfP, *newnP, *phP;
    cudaGetSymbolAddress((void**)&a1hi,  g_a1hi);
    cudaGetSymbolAddress((void**)&a1lo,  g_a1lo);
    cudaGetSymbolAddress((void**)&hidHi, g_hidhi);
    cudaGetSymbolAddress((void**)&hidLo, g_hidlo);
    cudaGetSymbolAddress((void**)&anhi,  g_anhi);
    cudaGetSymbolAddress((void**)&anlo,  g_anlo);
    cudaGetSymbolAddress((void**)&aphi,  g_aphi);
    cudaGetSymbolAddress((void**)&aplo,  g_aplo);
    cudaGetSymbolAddress((void**)&w1hi,  g_w1hi);
    cudaGetSymbolAddress((void**)&w1lo,  g_w1lo);
    cudaGetSymbolAddress((void**)&w2hi,  g_w2hi);
    cudaGetSymbolAddress((void**)&w2lo,  g_w2lo);
    cudaGetSymbolAddress((void**)&wnhi,  g_wnhi);
    cudaGetSymbolAddress((void**)&wnlo,  g_wnlo);
    cudaGetSymbolAddress((void**)&wphi,  g_wphi);
    cudaGetSymbolAddress((void**)&wplo,  g_wplo);
    cudaGetSymbolAddress((void**)&efP,   g_ef);
    cudaGetSymbolAddress((void**)&aP,    g_a);
    cudaGetSymbolAddress((void**)&exP,   g_ex);
    cudaGetSymbolAddress((void**)&mP,    g_m);
    cudaGetSymbolAddress((void**)&denP,  g_den);
    cudaGetSymbolAddress((void**)&zfP,   g_zf);
    cudaGetSymbolAddress((void**)&newnP, g_newn);
    cudaGetSymbolAddress((void**)&phP,   g_ph);

    cudaFuncSetAttribute(mma_gemm<true,  true>,  cudaFuncAttributeMaxDynamicSharedMemorySize, SMEM_MMA);
    cudaFuncSetAttribute(mma_gemm<false, false>, cudaFuncAttributeMaxDynamicSharedMemorySize, SMEM_MMA);
    cudaFuncSetAttribute(mma_gemm<false, true>,  cudaFuncAttributeMaxDynamicSharedMemorySize, SMEM_MMA);

    // 0) weight prep + softmax init + GEMM1 A prep
    transpose_split<<<dim3(CH / 32, K1 / 32), dim3(32, 8)>>>(We1, w1hi, w1lo, K1, CH);
    transpose_split<<<dim3(CD / 32, CH / 32), dim3(32, 8)>>>(We2, w2hi, w2lo, CH, CD);
    transpose_split<<<dim3(CD / 32, CH / 32), dim3(32, 8)>>>(Wn,  wnhi, wnlo, CH, CD);
    transpose_split<<<dim3(CD / 32, K1 / 32), dim3(32, 8)>>>(Wp1, wphi, wplo, K1, CD);
    init_kernel<<<(CN * CD + 255) / 256, 256>>>(mP, denP, zfP);
    split_gather_edge<<<CE, 288>>>(n_f, s_f, src, dst, a1hi, a1lo);

    // 1) hidden(hi/lo) = relu(A1 @ We1 + be1)                       [E,1024]
    mma_gemm<true, true><<<dim3(CH / 128, CE / 128), 128, SMEM_MMA>>>(
        CE, CH, K1, a1hi, a1lo, w1hi, w1lo, be1, hidHi, hidLo, nullptr);

    // 2) e_f = hidden @ We2 + be2                                   [E,512]
    mma_gemm<false, false><<<dim3(CD / 128, CE / 128), 128, SMEM_MMA>>>(
        CE, CD, CH, hidHi, hidLo, w2hi, w2lo, be2, nullptr, nullptr, efP);

    // 3-5) segment softmax + scatter
    edge_logit_kernel<<<CE / 8, 256>>>(efP, Wa, ba, dst, aP, mP);
    edge_exp_kernel<<<(CE + 255) / 256, 256>>>(aP, dst, mP, exP, denP);
    scatter_z_kernel<<<CE, 128>>>(n_f, efP, src, dst, exP, denP, zfP);

    // 6) new_n = concat(n_f, z_f) @ Wn + bn                         [N,512]
    split_node<<<CN_PAD, 256>>>(n_f, zfP, anhi, anlo);
    mma_gemm<false, false><<<dim3(CD / 128, CN_PAD / 128), 128, SMEM_MMA>>>(
        CN, CD, CH, anhi, anlo, wnhi, wnlo, bn, nullptr, nullptr, newnP);

    // 7) ph = relu(concat(new_n[sp], s_f[pe], new_n[dp]) @ Wp1 + bp1)   [P,512]
    split_pred<<<CP_PAD, 288>>>(newnP, s_f, src, dst, pidx, aphi, aplo);
    mma_gemm<false, true><<<dim3(CD / 128, CP_PAD / 128), 128, SMEM_MMA>>>(
        CP, CD, K1, aphi, aplo, wphi, wplo, bp1, nullptr, nullptr, phP);

    // 8) pred = ph @ Wp2 + bp2
    pred_kernel<<<CP / 8, 256>>>(phP, Wp2, bp2, out);
}

// round 7
// speedup vs baseline: 1.1077x; 1.1077x over previous
#include <cuda_runtime.h>
#include <cuda_fp16.h>
#include <cstdint>

// Problem dimensions (fixed by the dataset)
#define CN 20000
#define CE 160000
#define CP 10000
#define CD 512
#define CS 128
#define CH 1024
#define K1 (2*CD+CS)   // 1152

#define CN_PAD 20096   // 157 * 128
#define CP_PAD 10112   // 79 * 128

// ---------------------------------------------------------------------------
// Static device scratch (no allocations allowed)
// ---------------------------------------------------------------------------
__device__ __half g_hidhi[(size_t)CE * CH];     // relu(h@We1+be1) hi/lo
__device__ __half g_hidlo[(size_t)CE * CH];
__device__ __half g_anhi[(size_t)CN_PAD * CH];  // node GEMM A pre-split
__device__ __half g_anlo[(size_t)CN_PAD * CH];
__device__ __half g_aphi[(size_t)CP_PAD * K1];  // pred GEMM A pre-split
__device__ __half g_aplo[(size_t)CP_PAD * K1];
__device__ __half g_w1hi[(size_t)CH * K1];      // We1^T
__device__ __half g_w1lo[(size_t)CH * K1];
__device__ __half g_w2hi[(size_t)CD * CH];      // We2^T
__device__ __half g_w2lo[(size_t)CD * CH];
__device__ __half g_wnhi[(size_t)CD * CH];      // Wn^T
__device__ __half g_wnlo[(size_t)CD * CH];
__device__ __half g_wphi[(size_t)CD * K1];      // Wp1^T
__device__ __half g_wplo[(size_t)CD * K1];
__device__ float g_ef[(size_t)CE * CD];         // e_f  [E,512]
__device__ float g_a[CE];
__device__ float g_ex[CE];
__device__ float g_m[CN];
__device__ float g_den[CN];
__device__ float g_zf[(size_t)CN * CD];
__device__ float g_newn[(size_t)CN * CD];
__device__ float g_ph[(size_t)CP * CD];

// ---------------------------------------------------------------------------
// PTX helpers (all sm_80-class: assemble on plain sm_100)
// ---------------------------------------------------------------------------
__device__ __forceinline__ uint32_t smem_u32(const void* p) {
    uint32_t a;
    asm("{ .reg .u64 t; cvta.to.shared.u64 t, %1; cvt.u32.u64 %0, t; }" : "=r"(a) : "l"(p));
    return a;
}
__device__ __forceinline__ void ldsm_x4(uint32_t* r, uint32_t addr) {
    asm volatile("ldmatrix.sync.aligned.m8n8.x4.shared.b16 {%0,%1,%2,%3}, [%4];"
                 : "=r"(r[0]), "=r"(r[1]), "=r"(r[2]), "=r"(r[3]) : "r"(addr));
}
__device__ __forceinline__ void mma16816(float* d, const uint32_t* a,
                                         const uint32_t b0, const uint32_t b1) {
    asm volatile(
        "mma.sync.aligned.m16n8k16.row.col.f32.f16.f16.f32 "
        "{%0,%1,%2,%3}, {%4,%5,%6,%7}, {%8,%9}, {%0,%1,%2,%3};"
        : "+f"(d[0]), "+f"(d[1]), "+f"(d[2]), "+f"(d[3])
        : "r"(a[0]), "r"(a[1]), "r"(a[2]), "r"(a[3]), "r"(b0), "r"(b1));
}
__device__ __forceinline__ void cp16(uint32_t dst, const void* src) {
    asm volatile("cp.async.cg.shared.global [%0], [%1], 16;"
                 :: "r"(dst), "l"(__cvta_generic_to_global(src)) : "memory");
}
#define CP_COMMIT() asm volatile("cp.async.commit_group;" ::: "memory")
#define CP_WAIT1()  asm volatile("cp.async.wait_group 1;" ::: "memory")

__device__ __forceinline__ uint32_t packh(__half a, __half b) {
    return (uint32_t)__half_as_ushort(a) | ((uint32_t)__half_as_ushort(b) << 16);
}
__device__ __forceinline__ void splitH2(float x0, float x1, uint32_t& hi, uint32_t& lo) {
    __half h0 = __float2half_rn(x0);
    __half h1 = __float2half_rn(x1);
    float r0 = x0 - __half2float(h0);
    float r1 = x1 - __half2float(h1);
    hi = packh(h0, h1);
    lo = packh(__float2half_rn(r0), __float2half_rn(r1));
}

// ---------------------------------------------------------------------------
// Split-fp16 3-pass tensor GEMM.  C[M,Ntot] = act(A @ B^T + bias)
// CTA tile 128x256, 256 threads, 8 warps (2m x 4n), warp tile 64x64, BK=32,
// 3-stage pipeline.  B (and A when !GATHER) via cp.async; XOR-swizzled rows.
// GATHER: A row r = concat(n_f[src[r]], s_f[r], n_f[dst[r]]) fp32, split
//         in-register to fp16 hi/lo, stored to smem via STS.
// OUTH: epilogue writes fp16 hi/lo pair; else fp32. RELU optional.
// ---------------------------------------------------------------------------
#define AMATB  8192u                     // 128 rows x 64B
#define BMATB  16384u                    // 256 rows x 64B
#define STAGEB 49152u                    // Ah Al Bh Bl
#define SMEM_MMA (3 * STAGEB + 1024)     // + gather indices

template <bool GATHER, bool OUTH, bool RELU>
__global__ void __launch_bounds__(256, 1)
mma_gemm(int M, int Ntot, int Ktot,
         const float* __restrict__ nf, const float* __restrict__ sf,
         const int* __restrict__ srcI, const int* __restrict__ dstI,
         const __half* __restrict__ Ahi, const __half* __restrict__ Alo,
         const __half* __restrict__ Bhi, const __half* __restrict__ Blo,
         const float* __restrict__ bias,
         __half* __restrict__ outHi, __half* __restrict__ outLo,
         float* __restrict__ outF)
{
    extern __shared__ char smem[];
    const uint32_t sb = smem_u32(smem);
    int* i0s = (int*)(smem + 3 * STAGEB);
    int* i2s = i0s + 128;

    const int tid  = threadIdx.x;
    const int wid  = tid >> 5, lane = tid & 31;
    const int warpM = wid & 1, warpN = wid >> 1;          // 2 x 4
    const int rowBase = blockIdx.y * 128;
    const int colBase = blockIdx.x * 256;

    // A-load geometry: 2 threads/row (16 halves each); B: 1 thread/row
    const int am = tid >> 1, ah_ = tid & 1;
    const uint32_t axor = ((uint32_t)(am >> 1) & 3);
    const uint32_t bxor = ((uint32_t)(tid >> 1) & 3);

    if (GATHER) {
        if (tid < 128) {
            i0s[tid] = srcI[rowBase + tid];
            i2s[tid] = dstI[rowBase + tid];
        }
        __syncthreads();
    }

    float fA[16];   // gather-mode A prefetch registers

    auto ldgA = [&](int c) {             // GATHER only
        const int k = (c << 5) + ah_ * 16;
        const float* p;
        if (k < CD)            p = nf + (size_t)i0s[am] * CD + k;
        else if (k < CD + CS)  p = sf + (size_t)(rowBase + am) * CS + (k - CD);
        else                   p = nf + (size_t)i2s[am] * CD + (k - CD - CS);
#pragma unroll
        for (int j = 0; j < 4; j++) ((float4*)fA)[j] = ((const float4*)p)[j];
    };
    auto stsA = [&](int st) {            // GATHER only: split + STS
        uint32_t hi[8], lo[8];
#pragma unroll
        for (int j = 0; j < 8; j++) splitH2(fA[2 * j], fA[2 * j + 1], hi[j], lo[j]);
        const uint32_t base = (uint32_t)st * STAGEB + (uint32_t)am * 64u;
#pragma unroll
        for (int t = 0; t < 2; t++) {
            const uint32_t d = (((uint32_t)(ah_ * 2 + t)) ^ axor) * 16u;
            *(uint4*)(smem + base + d)         = *(uint4*)(hi + t * 4);
            *(uint4*)(smem + base + AMATB + d) = *(uint4*)(lo + t * 4);
        }
    };
    auto cpStage = [&](int st, int c) {
        const int k0 = c << 5;
        const uint32_t base = sb + (uint32_t)st * STAGEB;
        if (!GATHER) {
            const size_t aOff = (size_t)(rowBase + am) * Ktot + k0 + ah_ * 16;
#pragma unroll
            for (int t = 0; t < 2; t++) {
                const uint32_t d = (uint32_t)am * 64u + (((uint32_t)(ah_ * 2 + t)) ^ axor) * 16u;
                cp16(base + d,         Ahi + aOff + t * 8);
                cp16(base + AMATB + d, Alo + aOff + t * 8);
            }
        }
        const size_t bOff = (size_t)(colBase + tid) * Ktot + k0;
#pragma unroll
        for (int q = 0; q < 4; q++) {
            const uint32_t d = (uint32_t)tid * 64u + (((uint32_t)q) ^ bxor) * 16u;
            cp16(base + 2 * AMATB + d,         Bhi + bOff + q * 8);
            cp16(base + 2 * AMATB + BMATB + d, Blo + bOff + q * 8);
        }
    };

    float acc[4][8][4];
#pragma unroll
    for (int a = 0; a < 4; a++)
#pragma unroll
        for (int b = 0; b < 8; b++)
#pragma unroll
            for (int c = 0; c < 4; c++) acc[a][b][c] = 0.f;

    const int NCH = Ktot >> 5;

    // prologue
    if (GATHER) { ldgA(0); stsA(0); }
    cpStage(0, 0); CP_COMMIT();
    cpStage(1, 1); CP_COMMIT();
    if (GATHER) ldgA(1);

    const uint32_t xl = ((uint32_t)lane >> 1) & 3u;
    uint32_t lsel[2];
#pragma unroll
    for (int s = 0; s < 2; s++)
        lsel[s] = (uint32_t)(lane & 15) * 64u +
                  ((((uint32_t)s * 2u + ((uint32_t)lane >> 4)) ^ xl) * 16u);

    for (int c = 0; c < NCH; c++) {
        CP_WAIT1();
        __syncthreads();
        if (GATHER && c + 1 < NCH) stsA((c + 1) % 3);
        if (c + 2 < NCH) {
            cpStage((c + 2) % 3, c + 2);
            if (GATHER) ldgA(c + 2);
        }
        CP_COMMIT();   // uniform group accounting

        const uint32_t stb = sb + (uint32_t)(c % 3) * STAGEB;
        const uint32_t aH = stb, aL = stb + AMATB;
        const uint32_t bH = stb + 2 * AMATB, bL = stb + 2 * AMATB + BMATB;

#pragma unroll
        for (int s = 0; s < 2; s++) {
            uint32_t ahf[4][4], alf[4][4], bhf[4][4], blf[4][4];
#pragma unroll
            for (int mt = 0; mt < 4; mt++) {
                const uint32_t ro = (uint32_t)(warpM * 64 + mt * 16) * 64u + lsel[s];
                ldsm_x4(ahf[mt], aH + ro);
                ldsm_x4(alf[mt], aL + ro);
            }
#pragma unroll
            for (int i = 0; i < 4; i++) {
                const uint32_t ro = (uint32_t)(warpN * 64 + i * 16) * 64u + lsel[s];
                ldsm_x4(bhf[i], bH + ro);
                ldsm_x4(blf[i], bL + ro);
            }
#pragma unroll
            for (int mt = 0; mt < 4; mt++)
#pragma unroll
                for (int nt = 0; nt < 8; nt++)
                    mma16816(acc[mt][nt], ahf[mt], bhf[nt >> 1][nt & 1], bhf[nt >> 1][2 + (nt & 1)]);
#pragma unroll
            for (int mt = 0; mt < 4; mt++)
#pragma unroll
                for (int nt = 0; nt < 8; nt++)
                    mma16816(acc[mt][nt], ahf[mt], blf[nt >> 1][nt & 1], blf[nt >> 1][2 + (nt & 1)]);
#pragma unroll
            for (int mt = 0; mt < 4; mt++)
#pragma unroll
                for (int nt = 0; nt < 8; nt++)
                    mma16816(acc[mt][nt], alf[mt], bhf[nt >> 1][nt & 1], bhf[nt >> 1][2 + (nt & 1)]);
        }
    }

    // epilogue
#pragma unroll
    for (int mt = 0; mt < 4; mt++) {
        const int r0 = rowBase + warpM * 64 + mt * 16 + (lane >> 2);
#pragma unroll
        for (int nt = 0; nt < 8; nt++) {
            const int c0 = colBase + warpN * 64 + nt * 8 + (lane & 3) * 2;
            const float b0 = bias[c0], b1 = bias[c0 + 1];
            float v00 = acc[mt][nt][0] + b0, v01 = acc[mt][nt][1] + b1;
            float v10 = acc[mt][nt][2] + b0, v11 = acc[mt][nt][3] + b1;
            if (RELU) {
                v00 = fmaxf(v00, 0.f); v01 = fmaxf(v01, 0.f);
                v10 = fmaxf(v10, 0.f); v11 = fmaxf(v11, 0.f);
            }
            if (OUTH) {
                uint32_t h, l;
                if (r0 < M) {
                    splitH2(v00, v01, h, l);
                    *(uint32_t*)(outHi + (size_t)r0 * Ntot + c0) = h;
                    *(uint32_t*)(outLo + (size_t)r0 * Ntot + c0) = l;
                }
                if (r0 + 8 < M) {
                    splitH2(v10, v11, h, l);
                    *(uint32_t*)(outHi + (size_t)(r0 + 8) * Ntot + c0) = h;
                    *(uint32_t*)(outLo + (size_t)(r0 + 8) * Ntot + c0) = l;
                }
            } else {
                if (r0 < M)
                    *(float2*)(outF + (size_t)r0 * Ntot + c0) = make_float2(v00, v01);
                if (r0 + 8 < M)
                    *(float2*)(outF + (size_t)(r0 + 8) * Ntot + c0) = make_float2(v10, v11);
            }
        }
    }
}

// ---------------------------------------------------------------------------
// A-operand prep kernels (node/pred only): gather + fp32 -> fp16 hi/lo split
// ---------------------------------------------------------------------------
__global__ void split_node(const float* __restrict__ nf, const float* __restrict__ zf,
                           __half* __restrict__ hi, __half* __restrict__ lo)
{
    const int r = blockIdx.x;                  // 0..CN_PAD-1
    const int rs = r < CN ? r : CN - 1;
    const int j = threadIdx.x * 4;             // 256 threads -> 1024
    const float* p = (j < CD) ? (nf + (size_t)rs * CD + j)
                              : (zf + (size_t)rs * CD + (j - CD));
    float4 v = *(const float4*)p;
    uint32_t h0, l0, h1, l1;
    splitH2(v.x, v.y, h0, l0);
    splitH2(v.z, v.w, h1, l1);
    size_t o = (size_t)r * CH + j;
    *(uint2*)(hi + o) = make_uint2(h0, h1);
    *(uint2*)(lo + o) = make_uint2(l0, l1);
}

__global__ void split_pred(const float* __restrict__ newn, const float* __restrict__ sf,
                           const int* __restrict__ src, const int* __restrict__ dst,
                           const int* __restrict__ pidx,
                           __half* __restrict__ hi, __half* __restrict__ lo)
{
    const int r = blockIdx.x;                  // 0..CP_PAD-1
    const int rp = r < CP ? r : CP - 1;
    const int pe = pidx[rp];
    const int j = threadIdx.x * 4;             // 288 threads -> 1152
    const float* p;
    if (j < CD)            p = newn + (size_t)src[pe] * CD + j;
    else if (j < CD + CS)  p = sf + (size_t)pe * CS + (j - CD);
    else                   p = newn + (size_t)dst[pe] * CD + (j - CD - CS);
    float4 v = *(const float4*)p;
    uint32_t h0, l0, h1, l1;
    splitH2(v.x, v.y, h0, l0);
    splitH2(v.z, v.w, h1, l1);
    size_t o = (size_t)r * K1 + j;
    *(uint2*)(hi + o) = make_uint2(h0, h1);
    *(uint2*)(lo + o) = make_uint2(l0, l1);
}

// Weight prep: W[K][N] fp32 -> Wt hi/lo [N][K] fp16 (tiled transpose)
__global__ void transpose_split(const float* __restrict__ W,
                                __half* __restrict__ hi,
                                __half* __restrict__ lo,
                                int K, int N)
{
    __shared__ float t[32][33];
    const int nb = blockIdx.x * 32, kb = blockIdx.y * 32;
    const int x = threadIdx.x, y = threadIdx.y;   // (32,8)
#pragma unroll
    for (int i = 0; i < 32; i += 8)
        t[y + i][x] = W[(size_t)(kb + y + i) * N + nb + x];
    __syncthreads();
#pragma unroll
    for (int i = 0; i < 32; i += 8) {
        float v = t[x][y + i];
        __half h = __float2half_rn(v);
        size_t o = (size_t)(nb + y + i) * K + kb + x;
        hi[o] = h;
        lo[o] = __float2half_rn(v - __half2float(h));
    }
}

// ---------------------------------------------------------------------------
// Segment softmax + scatter
// ---------------------------------------------------------------------------
__device__ __forceinline__ void atomicMaxFloat(float* addr, float value) {
    if (value >= 0.f)
        atomicMax((int*)addr, __float_as_int(value));
    else
        atomicMin((unsigned int*)addr, __float_as_uint(value));
}

__global__ void init_kernel(float* __restrict__ m, float* __restrict__ den,
                            float* __restrict__ zf)
{
    size_t i = (size_t)blockIdx.x * 256 + threadIdx.x;
    if (i < (size_t)CN * CD) zf[i] = 0.f;
    if (i < CN) { m[i] = __int_as_float(0xff800000); den[i] = 0.f; }
}

__global__ void edge_logit_kernel(const float* __restrict__ ef,
                                  const float* __restrict__ Wa,
                                  const float* __restrict__ ba,
                                  const int*   __restrict__ dst,
                                  float* __restrict__ a,
                                  float* __restrict__ m)
{
    int e    = blockIdx.x * 8 + (threadIdx.x >> 5);
    int lane = threadIdx.x & 31;
    if (e >= CE) return;
    const float4* row = (const float4*)(ef + (size_t)e * CD);
    const float4* w   = (const float4*)Wa;
    float s = 0.f;
#pragma unroll
    for (int i = 0; i < 4; i++) {
        float4 v  = row[lane + i * 32];
        float4 wv = w[lane + i * 32];
        s += v.x * wv.x + v.y * wv.y + v.z * wv.z + v.w * wv.w;
    }
#pragma unroll
    for (int o = 16; o; o >>= 1) s += __shfl_xor_sync(0xffffffffu, s, o);
    if (lane == 0) {
        s += ba[0];
        a[e] = s;
        atomicMaxFloat(&m[dst[e]], s);
    }
}

__global__ void edge_exp_kernel(const float* __restrict__ a,
                                const int*   __restrict__ dst,
                                const float* __restrict__ m,
                                float* __restrict__ ex,
                                float* __restrict__ den)
{
    int e = blockIdx.x * 256 + threadIdx.x;
    if (e >= CE) return;
    int d = dst[e];
    float v = expf(a[e] - m[d]);
    ex[e] = v;
    atomicAdd(&den[d], v);
}

__global__ void scatter_z_kernel(const float* __restrict__ nf,
                                 const float* __restrict__ ef,
                                 const int*   __restrict__ src,
                                 const int*   __restrict__ dst,
                                 const float* __restrict__ ex,
                                 const float* __restrict__ den,
                                 float* __restrict__ zf)
{
    int e = blockIdx.x;
    int t = threadIdx.x;
    int d = dst[e], s = src[e];
    float alpha = ex[e] / den[d];
    float4 v = *(const float4*)(nf + (size_t)s * CD + t * 4);
    float4 w = *(const float4*)(ef + (size_t)e * CD + t * 4);
    float* zp = zf + (size_t)d * CD + t * 4;
    atomicAdd(zp + 0, alpha * (v.x + w.x));
    atomicAdd(zp + 1, alpha * (v.y + w.y));
    atomicAdd(zp + 2, alpha * (v.z + w.z));
    atomicAdd(zp + 3, alpha * (v.w + w.w));
}

__global__ void pred_kernel(const float* __restrict__ ph,
                            const float* __restrict__ Wp2,
                            const float* __restrict__ bp2,
                            float* __restrict__ out)
{
    int p    = blockIdx.x * 8 + (threadIdx.x >> 5);
    int lane = threadIdx.x & 31;
    if (p >= CP) return;
    const float4* row = (const float4*)(ph + (size_t)p * CD);
    const float4* w   = (const float4*)Wp2;
    float s = 0.f;
#pragma unroll
    for (int i = 0; i < 4; i++) {
        float4 v  = row[lane + i * 32];
        float4 wv = w[lane + i * 32];
        s += v.x * wv.x + v.y * wv.y + v.z * wv.z + v.w * wv.w;
    }
#pragma unroll
    for (int o = 16; o; o >>= 1) s += __shfl_xor_sync(0xffffffffu, s, o);
    if (lane == 0) out[p] = s + bp2[0];
}

// ---------------------------------------------------------------------------
// Launch
// ---------------------------------------------------------------------------
extern "C" void kernel_launch(void* const* d_in, const int* in_sizes, int n_in,
                              void* d_out, int out_size)
{
    const float* n_f  = (const float*)d_in[0];
    const float* s_f  = (const float*)d_in[1];
    const float* We1  = (const float*)d_in[2];
    const float* be1  = (const float*)d_in[3];
    const float* We2  = (const float*)d_in[4];
    const float* be2  = (const float*)d_in[5];
    const float* Wa   = (const float*)d_in[6];
    const float* ba   = (const float*)d_in[7];
    const float* Wn   = (const float*)d_in[8];
    const float* bn   = (const float*)d_in[9];
    const float* Wp1  = (const float*)d_in[10];
    const float* bp1  = (const float*)d_in[11];
    const float* Wp2  = (const float*)d_in[12];
    const float* bp2  = (const float*)d_in[13];
    const int*   src  = (const int*)d_in[14];
    const int*   dst  = (const int*)d_in[15];
    const int*   pidx = (const int*)d_in[16];
    float* out = (float*)d_out;

    __half *hidHi, *hidLo, *anhi, *anlo, *aphi, *aplo;
    __half *w1hi, *w1lo, *w2hi, *w2lo, *wnhi, *wnlo, *wphi, *wplo;
    float *efP, *aP, *exP, *mP, *denP, *zfP, *newnP, *phP;
    cudaGetSymbolAddress((void**)&hidHi, g_hidhi);
    cudaGetSymbolAddress((void**)&hidLo, g_hidlo);
    cudaGetSymbolAddress((void**)&anhi,  g_anhi);
    cudaGetSymbolAddress((void**)&anlo,  g_anlo);
    cudaGetSymbolAddress((void**)&aphi,  g_aphi);
    cudaGetSymbolAddress((void**)&aplo,  g_aplo);
    cudaGetSymbolAddress((void**)&w1hi,  g_w1hi);
    cudaGetSymbolAddress((void**)&w1lo,  g_w1lo);
    cudaGetSymbolAddress((void**)&w2hi,  g_w2hi);
    cudaGetSymbolAddress((void**)&w2lo,  g_w2lo);
    cudaGetSymbolAddress((void**)&wnhi,  g_wnhi);
    cudaGetSymbolAddress((void**)&wnlo,  g_wnlo);
    cudaGetSymbolAddress((void**)&wphi,  g_wphi);
    cudaGetSymbolAddress((void**)&wplo,  g_wplo);
    cudaGetSymbolAddress((void**)&efP,   g_ef);
    cudaGetSymbolAddress((void**)&aP,    g_a);
    cudaGetSymbolAddress((void**)&exP,   g_ex);
    cudaGetSymbolAddress((void**)&mP,    g_m);
    cudaGetSymbolAddress((void**)&denP,  g_den);
    cudaGetSymbolAddress((void**)&zfP,   g_zf);
    cudaGetSymbolAddress((void**)&newnP, g_newn);
    cudaGetSymbolAddress((void**)&phP,   g_ph);

    cudaFuncSetAttribute(mma_gemm<true,  true,  true>,
                         cudaFuncAttributeMaxDynamicSharedMemorySize, SMEM_MMA);
    cudaFuncSetAttribute(mma_gemm<false, false, false>,
                         cudaFuncAttributeMaxDynamicSharedMemorySize, SMEM_MMA);
    cudaFuncSetAttribute(mma_gemm<false, false, true>,
                         cudaFuncAttributeMaxDynamicSharedMemorySize, SMEM_MMA);

    // 0) weight prep + softmax init
    transpose_split<<<dim3(CH / 32, K1 / 32), dim3(32, 8)>>>(We1, w1hi, w1lo, K1, CH);
    transpose_split<<<dim3(CD / 32, CH / 32), dim3(32, 8)>>>(We2, w2hi, w2lo, CH, CD);
    transpose_split<<<dim3(CD / 32, CH / 32), dim3(32, 8)>>>(Wn,  wnhi, wnlo, CH, CD);
    transpose_split<<<dim3(CD / 32, K1 / 32), dim3(32, 8)>>>(Wp1, wphi, wplo, K1, CD);
    init_kernel<<<(CN * CD + 255) / 256, 256>>>(mP, denP, zfP);

    // 1) hidden(hi/lo) = relu(concat(n_f[src], s_f, n_f[dst]) @ We1 + be1)  [E,1024]
    mma_gemm<true, true, true><<<dim3(CH / 256, CE / 128), 256, SMEM_MMA>>>(
        CE, CH, K1, n_f, s_f, src, dst,
        nullptr, nullptr, w1hi, w1lo, be1, hidHi, hidLo, nullptr);

    // 2) e_f = hidden @ We2 + be2                                           [E,512]
    mma_gemm<false, false, false><<<dim3(CD / 256, CE / 128), 256, SMEM_MMA>>>(
        CE, CD, CH, nullptr, nullptr, nullptr, nullptr,
        hidHi, hidLo, w2hi, w2lo, be2, nullptr, nullptr, efP);

    // 3-5) segment softmax + scatter
    edge_logit_kernel<<<CE / 8, 256>>>(efP, Wa, ba, dst, aP, mP);
    edge_exp_kernel<<<(CE + 255) / 256, 256>>>(aP, dst, mP, exP, denP);
    scatter_z_kernel<<<CE, 128>>>(n_f, efP, src, dst, exP, denP, zfP);

    // 6) new_n = concat(n_f, z_f) @ Wn + bn                                 [N,512]
    split_node<<<CN_PAD, 256>>>(n_f, zfP, anhi, anlo);
    mma_gemm<false, false, false><<<dim3(CD / 256, CN_PAD / 128), 256, SMEM_MMA>>>(
        CN, CD, CH, nullptr, nullptr, nullptr, nullptr,
        anhi, anlo, wnhi, wnlo, bn, nullptr, nullptr, newnP);

    // 7) ph = relu(concat(new_n[sp], s_f[pe], new_n[dp]) @ Wp1 + bp1)       [P,512]
    split_pred<<<CP_PAD, 288>>>(newnP, s_f, src, dst, pidx, aphi, aplo);
    mma_gemm<false, false, true><<<dim3(CD / 256, CP_PAD / 128), 256, SMEM_MMA>>>(
        CP, CD, K1, nullptr, nullptr, nullptr, nullptr,
        aphi, aplo, wphi, wplo, bp1, nullptr, nullptr, phP);

    // 8) pred = ph @ Wp2 + bp2
    pred_kernel<<<CP / 8, 256>>>(phP, Wp2, bp2, out);
}

// round 9
// speedup vs baseline: 1.8839x; 1.7008x over previous
#include <cuda_runtime.h>
#include <cuda_fp16.h>
#include <cstdint>

// Problem dimensions (fixed by the dataset)
#define CN 20000
#define CE 160000
#define CP 10000
#define CD 512
#define CS 128
#define CH 1024
#define K1 (2*CD+CS)   // 1152

#define CN_PAD 20096   // 157 * 128
#define CP_PAD 10112   // 79 * 128

// ---------------------------------------------------------------------------
// Static device scratch. Two big pools with lifetime-aliased tenants keep the
// total image under the 2GB small-code-model limit.
// poolA: S [E,1024] f32 (GEMM1b->fuse)  ->  e_f [E,512] f32 (GEMM2->scatter)
// poolB: sf split hi/lo (split->GEMM1b) -> hidden hi/lo (fuse->GEMM2)
//        -> an hi/lo + ap hi/lo (node/pred GEMM A operands)
// ---------------------------------------------------------------------------
#define POOLSZ ((size_t)CE * CH * 4)                 // 655,360,000 B
__device__ __align__(1024) char g_poolA[POOLSZ];
__device__ __align__(1024) char g_poolB[POOLSZ];

__device__ __half g_nfhi[(size_t)CN_PAD * CD];       // split n_f
__device__ __half g_nflo[(size_t)CN_PAD * CD];
__device__ float  g_uv[(size_t)CN_PAD * 2 * CH];     // [N, U(1024) | V(1024)]
__device__ __half g_wuvhi[(size_t)2 * CH * CD];      // [Wtop^T ; Wbot^T]
__device__ __half g_wuvlo[(size_t)2 * CH * CD];
__device__ __half g_wmhi[(size_t)CH * CS];           // Wmid^T  [1024,128]
__device__ __half g_wmlo[(size_t)CH * CS];
__device__ __half g_w2hi[(size_t)CD * CH];           // We2^T   [512,1024]
__device__ __half g_w2lo[(size_t)CD * CH];
__device__ __half g_wnhi[(size_t)CD * CH];           // Wn^T
__device__ __half g_wnlo[(size_t)CD * CH];
__device__ __half g_wphi[(size_t)CD * K1];           // Wp1^T
__device__ __half g_wplo[(size_t)CD * K1];
__device__ float  g_zero[2 * CH];                    // zero bias (zero-init)
__device__ float  g_a[CE];
__device__ float  g_ex[CE];
__device__ float  g_m[CN];
__device__ float  g_den[CN];
__device__ float  g_zf[(size_t)CN * CD];
__device__ float  g_newn[(size_t)CN * CD];
__device__ float  g_ph[(size_t)CP * CD];

// ---------------------------------------------------------------------------
// PTX helpers (all sm_80-class: assemble on plain sm_100)
// ---------------------------------------------------------------------------
__device__ __forceinline__ uint32_t smem_u32(const void* p) {
    uint32_t a;
    asm("{ .reg .u64 t; cvta.to.shared.u64 t, %1; cvt.u32.u64 %0, t; }" : "=r"(a) : "l"(p));
    return a;
}
__device__ __forceinline__ void ldsm_x4(uint32_t* r, uint32_t addr) {
    asm volatile("ldmatrix.sync.aligned.m8n8.x4.shared.b16 {%0,%1,%2,%3}, [%4];"
                 : "=r"(r[0]), "=r"(r[1]), "=r"(r[2]), "=r"(r[3]) : "r"(addr));
}
__device__ __forceinline__ void mma16816(float* d, const uint32_t* a,
                                         const uint32_t b0, const uint32_t b1) {
    asm volatile(
        "mma.sync.aligned.m16n8k16.row.col.f32.f16.f16.f32 "
        "{%0,%1,%2,%3}, {%4,%5,%6,%7}, {%8,%9}, {%0,%1,%2,%3};"
        : "+f"(d[0]), "+f"(d[1]), "+f"(d[2]), "+f"(d[3])
        : "r"(a[0]), "r"(a[1]), "r"(a[2]), "r"(a[3]), "r"(b0), "r"(b1));
}
__device__ __forceinline__ void cp16(uint32_t dst, const void* src) {
    asm volatile("cp.async.cg.shared.global [%0], [%1], 16;"
                 :: "r"(dst), "l"(__cvta_generic_to_global(src)) : "memory");
}
#define CP_COMMIT() asm volatile("cp.async.commit_group;" ::: "memory")
#define CP_WAIT1()  asm volatile("cp.async.wait_group 1;" ::: "memory")

__device__ __forceinline__ uint32_t packh(__half a, __half b) {
    return (uint32_t)__half_as_ushort(a) | ((uint32_t)__half_as_ushort(b) << 16);
}
__device__ __forceinline__ void splitH2(float x0, float x1, uint32_t& hi, uint32_t& lo) {
    __half h0 = __float2half_rn(x0);
    __half h1 = __float2half_rn(x1);
    float r0 = x0 - __half2float(h0);
    float r1 = x1 - __half2float(h1);
    hi = packh(h0, h1);
    lo = packh(__float2half_rn(r0), __float2half_rn(r1));
}

// ---------------------------------------------------------------------------
// Split-fp16 3-pass tensor GEMM.  C[M,Ntot] = (relu?)(A @ B^T + bias), fp32 out
// A: pre-split fp16 hi/lo [Mpad][Ktot]; B: pre-split [Ntot][Ktot] K-major.
// CTA tile 128x256, 256 threads, 8 warps (2m x 4n), warp tile 64x64, BK=32,
// 3-stage cp.async pipeline, XOR-swizzled 64B rows.
// ---------------------------------------------------------------------------
#define AMATB  8192u                     // 128 rows x 64B
#define BMATB  16384u                    // 256 rows x 64B
#define STAGEB 49152u                    // Ah Al Bh Bl
#define SMEM_MMA (3 * STAGEB)

template <bool RELU>
__global__ void __launch_bounds__(256, 1)
mma_gemm(int M, int Ntot, int Ktot,
         const __half* __restrict__ Ahi, const __half* __restrict__ Alo,
         const __half* __restrict__ Bhi, const __half* __restrict__ Blo,
         const float* __restrict__ bias,
         float* __restrict__ outF)
{
    extern __shared__ char smem[];
    const uint32_t sb = smem_u32(smem);

    const int tid  = threadIdx.x;
    const int wid  = tid >> 5, lane = tid & 31;
    const int warpM = wid & 1, warpN = wid >> 1;          // 2 x 4
    const int rowBase = blockIdx.y * 128;
    const int colBase = blockIdx.x * 256;

    const int am = tid >> 1, ah_ = tid & 1;               // A: 2 thr/row
    const uint32_t axor = ((uint32_t)(am >> 1) & 3);
    const uint32_t bxor = ((uint32_t)(tid >> 1) & 3);

    auto cpStage = [&](int st, int c) {
        const int k0 = c << 5;
        const uint32_t base = sb + (uint32_t)st * STAGEB;
        const size_t aOff = (size_t)(rowBase + am) * Ktot + k0 + ah_ * 16;
#pragma unroll
        for (int t = 0; t < 2; t++) {
            const uint32_t d = (uint32_t)am * 64u + (((uint32_t)(ah_ * 2 + t)) ^ axor) * 16u;
            cp16(base + d,         Ahi + aOff + t * 8);
            cp16(base + AMATB + d, Alo + aOff + t * 8);
        }
        const size_t bOff = (size_t)(colBase + tid) * Ktot + k0;
#pragma unroll
        for (int q = 0; q < 4; q++) {
            const uint32_t d = (uint32_t)tid * 64u + (((uint32_t)q) ^ bxor) * 16u;
            cp16(base + 2 * AMATB + d,         Bhi + bOff + q * 8);
            cp16(base + 2 * AMATB + BMATB + d, Blo + bOff + q * 8);
        }
    };

    float acc[4][8][4];
#pragma unroll
    for (int a = 0; a < 4; a++)
#pragma unroll
        for (int b = 0; b < 8; b++)
#pragma unroll
            for (int c = 0; c < 4; c++) acc[a][b][c] = 0.f;

    const int NCH = Ktot >> 5;

    cpStage(0, 0); CP_COMMIT();
    cpStage(1, 1); CP_COMMIT();

    const uint32_t xl = ((uint32_t)lane >> 1) & 3u;
    uint32_t lsel[2];
#pragma unroll
    for (int s = 0; s < 2; s++)
        lsel[s] = (uint32_t)(lane & 15) * 64u +
                  ((((uint32_t)s * 2u + ((uint32_t)lane >> 4)) ^ xl) * 16u);

    for (int c = 0; c < NCH; c++) {
        CP_WAIT1();
        __syncthreads();
        if (c + 2 < NCH) cpStage((c + 2) % 3, c + 2);
        CP_COMMIT();

        const uint32_t stb = sb + (uint32_t)(c % 3) * STAGEB;
        const uint32_t aH = stb, aL = stb + AMATB;
        const uint32_t bH = stb + 2 * AMATB, bL = stb + 2 * AMATB + BMATB;

#pragma unroll
        for (int s = 0; s < 2; s++) {
            uint32_t ahf[4][4], alf[4][4], bhf[4][4], blf[4][4];
#pragma unroll
            for (int mt = 0; mt < 4; mt++) {
                const uint32_t ro = (uint32_t)(warpM * 64 + mt * 16) * 64u + lsel[s];
                ldsm_x4(ahf[mt], aH + ro);
                ldsm_x4(alf[mt], aL + ro);
            }
#pragma unroll
            for (int i = 0; i < 4; i++) {
                const uint32_t ro = (uint32_t)(warpN * 64 + i * 16) * 64u + lsel[s];
                ldsm_x4(bhf[i], bH + ro);
                ldsm_x4(blf[i], bL + ro);
            }
#pragma unroll
            for (int mt = 0; mt < 4; mt++)
#pragma unroll
                for (int nt = 0; nt < 8; nt++)
                    mma16816(acc[mt][nt], ahf[mt], bhf[nt >> 1][nt & 1], bhf[nt >> 1][2 + (nt & 1)]);
#pragma unroll
            for (int mt = 0; mt < 4; mt++)
#pragma unroll
                for (int nt = 0; nt < 8; nt++)
                    mma16816(acc[mt][nt], ahf[mt], blf[nt >> 1][nt & 1], blf[nt >> 1][2 + (nt & 1)]);
#pragma unroll
            for (int mt = 0; mt < 4; mt++)
#pragma unroll
                for (int nt = 0; nt < 8; nt++)
                    mma16816(acc[mt][nt], alf[mt], bhf[nt >> 1][nt & 1], bhf[nt >> 1][2 + (nt & 1)]);
        }
    }

    // epilogue (fp32 out)
#pragma unroll
    for (int mt = 0; mt < 4; mt++) {
        const int r0 = rowBase + warpM * 64 + mt * 16 + (lane >> 2);
#pragma unroll
        for (int nt = 0; nt < 8; nt++) {
            const int c0 = colBase + warpN * 64 + nt * 8 + (lane & 3) * 2;
            const float b0 = bias[c0], b1 = bias[c0 + 1];
            float v00 = acc[mt][nt][0] + b0, v01 = acc[mt][nt][1] + b1;
            float v10 = acc[mt][nt][2] + b0, v11 = acc[mt][nt][3] + b1;
            if (RELU) {
                v00 = fmaxf(v00, 0.f); v01 = fmaxf(v01, 0.f);
                v10 = fmaxf(v10, 0.f); v11 = fmaxf(v11, 0.f);
            }
            if (r0 < M)
                *(float2*)(outF + (size_t)r0 * Ntot + c0) = make_float2(v00, v01);
            if (r0 + 8 < M)
                *(float2*)(outF + (size_t)(r0 + 8) * Ntot + c0) = make_float2(v10, v11);
        }
    }
}

// ---------------------------------------------------------------------------
// hidden = relu(U[src[e]] + S[e] + V[dst[e]]) -> fp16 hi/lo     one block/edge
// ---------------------------------------------------------------------------
__global__ void fuse_hidden(const float* __restrict__ uv, const float* __restrict__ s,
                            const int* __restrict__ src, const int* __restrict__ dst,
                            __half* __restrict__ hi, __half* __restrict__ lo)
{
    const int e = blockIdx.x;
    const int j = threadIdx.x * 4;                 // 256 threads -> 1024
    const float4 u = *(const float4*)(uv + (size_t)src[e] * 2 * CH + j);
    const float4 v = *(const float4*)(uv + (size_t)dst[e] * 2 * CH + CH + j);
    const float4 sv = *(const float4*)(s + (size_t)e * CH + j);
    float x0 = fmaxf(u.x + v.x + sv.x, 0.f);
    float x1 = fmaxf(u.y + v.y + sv.y, 0.f);
    float x2 = fmaxf(u.z + v.z + sv.z, 0.f);
    float x3 = fmaxf(u.w + v.w + sv.w, 0.f);
    uint32_t h0, l0, h1, l1;
    splitH2(x0, x1, h0, l0);
    splitH2(x2, x3, h1, l1);
    size_t o = (size_t)e * CH + j;
    *(uint2*)(hi + o) = make_uint2(h0, h1);
    *(uint2*)(lo + o) = make_uint2(l0, l1);
}

// ---------------------------------------------------------------------------
// A-operand prep kernels: fp32 -> fp16 hi/lo split
// ---------------------------------------------------------------------------
__global__ void split_nf(const float* __restrict__ nf,
                         __half* __restrict__ hi, __half* __restrict__ lo)
{
    const int r = blockIdx.x;                      // 0..CN_PAD-1
    const int rs = r < CN ? r : CN - 1;
    const int j = threadIdx.x * 4;                 // 128 threads -> 512
    float4 v = *(const float4*)(nf + (size_t)rs * CD + j);
    uint32_t h0, l0, h1, l1;
    splitH2(v.x, v.y, h0, l0);
    splitH2(v.z, v.w, h1, l1);
    size_t o = (size_t)r * CD + j;
    *(uint2*)(hi + o) = make_uint2(h0, h1);
    *(uint2*)(lo + o) = make_uint2(l0, l1);
}

__global__ void split_sf(const float* __restrict__ sf,
                         __half* __restrict__ hi, __half* __restrict__ lo)
{
    const size_t idx = ((size_t)blockIdx.x * 256 + threadIdx.x) * 4;  // over E*128
    float4 v = *(const float4*)(sf + idx);
    uint32_t h0, l0, h1, l1;
    splitH2(v.x, v.y, h0, l0);
    splitH2(v.z, v.w, h1, l1);
    *(uint2*)(hi + idx) = make_uint2(h0, h1);
    *(uint2*)(lo + idx) = make_uint2(l0, l1);
}

__global__ void split_node(const float* __restrict__ nf, const float* __restrict__ zf,
                           __half* __restrict__ hi, __half* __restrict__ lo)
{
    const int r = blockIdx.x;                  // 0..CN_PAD-1
    const int rs = r < CN ? r : CN - 1;
    const int j = threadIdx.x * 4;             // 256 threads -> 1024
    const float* p = (j < CD) ? (nf + (size_t)rs * CD + j)
                              : (zf + (size_t)rs * CD + (j - CD));
    float4 v = *(const float4*)p;
    uint32_t h0, l0, h1, l1;
    splitH2(v.x, v.y, h0, l0);
    splitH2(v.z, v.w, h1, l1);
    size_t o = (size_t)r * CH + j;
    *(uint2*)(hi + o) = make_uint2(h0, h1);
    *(uint2*)(lo + o) = make_uint2(l0, l1);
}

__global__ void split_pred(const float* __restrict__ newn, const float* __restrict__ sf,
                           const int* __restrict__ src, const int* __restrict__ dst,
                           const int* __restrict__ pidx,
                           __half* __restrict__ hi, __half* __restrict__ lo)
{
    const int r = blockIdx.x;                  // 0..CP_PAD-1
    const int rp = r < CP ? r : CP - 1;
    const int pe = pidx[rp];
    const int j = threadIdx.x * 4;             // 288 threads -> 1152
    const float* p;
    if (j < CD)            p = newn + (size_t)src[pe] * CD + j;
    else if (j < CD + CS)  p = sf + (size_t)pe * CS + (j - CD);
    else                   p = newn + (size_t)dst[pe] * CD + (j - CD - CS);
    float4 v = *(const float4*)p;
    uint32_t h0, l0, h1, l1;
    splitH2(v.x, v.y, h0, l0);
    splitH2(v.z, v.w, h1, l1);
    size_t o = (size_t)r * K1 + j;
    *(uint2*)(hi + o) = make_uint2(h0, h1);
    *(uint2*)(lo + o) = make_uint2(l0, l1);
}

// ---------------------------------------------------------------------------
// Weight prep: out[(outRowOff+n)*Kst + k] = W[(rowOff+kb..)*WN + n], split hi/lo
// ---------------------------------------------------------------------------
__global__ void transpose_split(const float* __restrict__ W, int WN, int rowOff,
                                __half* __restrict__ hi, __half* __restrict__ lo,
                                int outRowOff, int Kst)
{
    __shared__ float t[32][33];
    const int nb = blockIdx.x * 32, kb = blockIdx.y * 32;
    const int x = threadIdx.x, y = threadIdx.y;   // (32,8)
#pragma unroll
    for (int i = 0; i < 32; i += 8)
        t[y + i][x] = W[(size_t)(rowOff + kb + y + i) * WN + nb + x];
    __syncthreads();
#pragma unroll
    for (int i = 0; i < 32; i += 8) {
        float v = t[x][y + i];
        __half h = __float2half_rn(v);
        size_t o = (size_t)(outRowOff + nb + y + i) * Kst + kb + x;
        hi[o] = h;
        lo[o] = __float2half_rn(v - __half2float(h));
    }
}

// ---------------------------------------------------------------------------
// Segment softmax + scatter
// ---------------------------------------------------------------------------
__device__ __forceinline__ void atomicMaxFloat(float* addr, float value) {
    if (value >= 0.f)
        atomicMax((int*)addr, __float_as_int(value));
    else
        atomicMin((unsigned int*)addr, __float_as_uint(value));
}

__global__ void init_kernel(float* __restrict__ m, float* __restrict__ den,
                            float* __restrict__ zf)
{
    size_t i = (size_t)blockIdx.x * 256 + threadIdx.x;
    if (i < (size_t)CN * CD) zf[i] = 0.f;
    if (i < CN) { m[i] = __int_as_float(0xff800000); den[i] = 0.f; }
}

__global__ void edge_logit_kernel(const float* __restrict__ ef,
                                  const float* __restrict__ Wa,
                                  const float* __restrict__ ba,
                                  const int*   __restrict__ dst,
                                  float* __restrict__ a,
                                  float* __restrict__ m)
{
    int e    = blockIdx.x * 8 + (threadIdx.x >> 5);
    int lane = threadIdx.x & 31;
    if (e >= CE) return;
    const float4* row = (const float4*)(ef + (size_t)e * CD);
    const float4* w   = (const float4*)Wa;
    float s = 0.f;
#pragma unroll
    for (int i = 0; i < 4; i++) {
        float4 v  = row[lane + i * 32];
        float4 wv = w[lane + i * 32];
        s += v.x * wv.x + v.y * wv.y + v.z * wv.z + v.w * wv.w;
    }
#pragma unroll
    for (int o = 16; o; o >>= 1) s += __shfl_xor_sync(0xffffffffu, s, o);
    if (lane == 0) {
        s += ba[0];
        a[e] = s;
        atomicMaxFloat(&m[dst[e]], s);
    }
}

__global__ void edge_exp_kernel(const float* __restrict__ a,
                                const int*   __restrict__ dst,
                                const float* __restrict__ m,
                                float* __restrict__ ex,
                                float* __restrict__ den)
{
    int e = blockIdx.x * 256 + threadIdx.x;
    if (e >= CE) return;
    int d = dst[e];
    float v = expf(a[e] - m[d]);
    ex[e] = v;
    atomicAdd(&den[d], v);
}

__global__ void scatter_z_kernel(const float* __restrict__ nf,
                                 const float* __restrict__ ef,
                                 const int*   __restrict__ src,
                                 const int*   __restrict__ dst,
                                 const float* __restrict__ ex,
                                 const float* __restrict__ den,
                                 float* __restrict__ zf)
{
    int e = blockIdx.x;
    int t = threadIdx.x;
    int d = dst[e], s = src[e];
    float alpha = ex[e] / den[d];
    float4 v = *(const float4*)(nf + (size_t)s * CD + t * 4);
    float4 w = *(const float4*)(ef + (size_t)e * CD + t * 4);
    float* zp = zf + (size_t)d * CD + t * 4;
    atomicAdd(zp + 0, alpha * (v.x + w.x));
    atomicAdd(zp + 1, alpha * (v.y + w.y));
    atomicAdd(zp + 2, alpha * (v.z + w.z));
    atomicAdd(zp + 3, alpha * (v.w + w.w));
}

__global__ void pred_kernel(const float* __restrict__ ph,
                            const float* __restrict__ Wp2,
                            const float* __restrict__ bp2,
                            float* __restrict__ out)
{
    int p    = blockIdx.x * 8 + (threadIdx.x >> 5);
    int lane = threadIdx.x & 31;
    if (p >= CP) return;
    const float4* row = (const float4*)(ph + (size_t)p * CD);
    const float4* w   = (const float4*)Wp2;
    float s = 0.f;
#pragma unroll
    for (int i = 0; i < 4; i++) {
        float4 v  = row[lane + i * 32];
        float4 wv = w[lane + i * 32];
        s += v.x * wv.x + v.y * wv.y + v.z * wv.z + v.w * wv.w;
    }
#pragma unroll
    for (int o = 16; o; o >>= 1) s += __shfl_xor_sync(0xffffffffu, s, o);
    if (lane == 0) out[p] = s + bp2[0];
}

// ---------------------------------------------------------------------------
// Launch
// ---------------------------------------------------------------------------
extern "C" void kernel_launch(void* const* d_in, const int* in_sizes, int n_in,
                              void* d_out, int out_size)
{
    const float* n_f  = (const float*)d_in[0];
    const float* s_f  = (const float*)d_in[1];
    const float* We1  = (const float*)d_in[2];
    const float* be1  = (const float*)d_in[3];
    const float* We2  = (const float*)d_in[4];
    const float* be2  = (const float*)d_in[5];
    const float* Wa   = (const float*)d_in[6];
    const float* ba   = (const float*)d_in[7];
    const float* Wn   = (const float*)d_in[8];
    const float* bn   = (const float*)d_in[9];
    const float* Wp1  = (const float*)d_in[10];
    const float* bp1  = (const float*)d_in[11];
    const float* Wp2  = (const float*)d_in[12];
    const float* bp2  = (const float*)d_in[13];
    const int*   src  = (const int*)d_in[14];
    const int*   dst  = (const int*)d_in[15];
    const int*   pidx = (const int*)d_in[16];
    float* out = (float*)d_out;

    char *poolA, *poolB;
    __half *nfhi, *nflo;
    __half *wuvhi, *wuvlo, *wmhi, *wmlo, *w2hi, *w2lo, *wnhi, *wnlo, *wphi, *wplo;
    float *uvP, *zeroP, *aP, *exP, *mP, *denP, *zfP, *newnP, *phP;
    cudaGetSymbolAddress((void**)&poolA, g_poolA);
    cudaGetSymbolAddress((void**)&poolB, g_poolB);
    cudaGetSymbolAddress((void**)&nfhi,  g_nfhi);
    cudaGetSymbolAddress((void**)&nflo,  g_nflo);
    cudaGetSymbolAddress((void**)&uvP,   g_uv);
    cudaGetSymbolAddress((void**)&wuvhi, g_wuvhi);
    cudaGetSymbolAddress((void**)&wuvlo, g_wuvlo);
    cudaGetSymbolAddress((void**)&wmhi,  g_wmhi);
    cudaGetSymbolAddress((void**)&wmlo,  g_wmlo);
    cudaGetSymbolAddress((void**)&w2hi,  g_w2hi);
    cudaGetSymbolAddress((void**)&w2lo,  g_w2lo);
    cudaGetSymbolAddress((void**)&wnhi,  g_wnhi);
    cudaGetSymbolAddress((void**)&wnlo,  g_wnlo);
    cudaGetSymbolAddress((void**)&wphi,  g_wphi);
    cudaGetSymbolAddress((void**)&wplo,  g_wplo);
    cudaGetSymbolAddress((void**)&zeroP, g_zero);
    cudaGetSymbolAddress((void**)&aP,    g_a);
    cudaGetSymbolAddress((void**)&exP,   g_ex);
    cudaGetSymbolAddress((void**)&mP,    g_m);
    cudaGetSymbolAddress((void**)&denP,  g_den);
    cudaGetSymbolAddress((void**)&zfP,   g_zf);
    cudaGetSymbolAddress((void**)&newnP, g_newn);
    cudaGetSymbolAddress((void**)&phP,   g_ph);

    // --- pool tenants (lifetimes are strictly sequential on the stream) ---
    // poolA: S [E,1024] f32  -> e_f [E,512] f32
    float*  sP    = (float*)poolA;
    float*  efP   = (float*)poolA;
    // poolB phase 1: split s_f hi/lo (2 x 40.96 MB)
    __half* sfhi  = (__half*)poolB;
    __half* sflo  = (__half*)(poolB + (size_t)CE * CS * 2);
    // poolB phase 2: hidden hi/lo (2 x 327.68 MB; overwrites sf after GEMM1b)
    __half* hidHi = (__half*)poolB;
    __half* hidLo = (__half*)(poolB + (size_t)CE * CH * 2);
    // poolB phase 3: node/pred A operands (after GEMM2 consumed hidden)
    __half* anhi  = (__half*)poolB;
    __half* anlo  = (__half*)(poolB + (size_t)CN_PAD * CH * 2);
    __half* aphi  = (__half*)(poolB + (size_t)CN_PAD * CH * 4);
    __half* aplo  = (__half*)(poolB + (size_t)CN_PAD * CH * 4 + (size_t)CP_PAD * K1 * 2);

    cudaFuncSetAttribute(mma_gemm<false>, cudaFuncAttributeMaxDynamicSharedMemorySize, SMEM_MMA);
    cudaFuncSetAttribute(mma_gemm<true>,  cudaFuncAttributeMaxDynamicSharedMemorySize, SMEM_MMA);

    // 0) weight prep:  g_wuv = [Wtop^T ; Wbot^T], g_wm = Wmid^T, plus We2/Wn/Wp1
    transpose_split<<<dim3(CH / 32, CD / 32), dim3(32, 8)>>>(We1, CH, 0,   wuvhi, wuvlo, 0,  CD);
    transpose_split<<<dim3(CH / 32, CD / 32), dim3(32, 8)>>>(We1, CH, 640, wuvhi, wuvlo, CH, CD);
    transpose_split<<<dim3(CH / 32, CS / 32), dim3(32, 8)>>>(We1, CH, 512, wmhi,  wmlo,  0,  CS);
    transpose_split<<<dim3(CD / 32, CH / 32), dim3(32, 8)>>>(We2, CD, 0,   w2hi,  w2lo,  0,  CH);
    transpose_split<<<dim3(CD / 32, CH / 32), dim3(32, 8)>>>(Wn,  CD, 0,   wnhi,  wnlo,  0,  CH);
    transpose_split<<<dim3(CD / 32, K1 / 32), dim3(32, 8)>>>(Wp1, CD, 0,   wphi,  wplo,  0,  K1);
    init_kernel<<<(CN * CD + 255) / 256, 256>>>(mP, denP, zfP);
    split_nf<<<CN_PAD, 128>>>(n_f, nfhi, nflo);
    split_sf<<<(CE * CS / 4) / 256, 256>>>(s_f, sfhi, sflo);

    // 1a) [U|V] = n_f @ [Wtop Wbot]           [N, 2048]
    mma_gemm<false><<<dim3(2 * CH / 256, CN_PAD / 128), 256, SMEM_MMA>>>(
        CN, 2 * CH, CD, nfhi, nflo, wuvhi, wuvlo, zeroP, uvP);

    // 1b) S = s_f @ Wmid + be1                [E, 1024]
    mma_gemm<false><<<dim3(CH / 256, CE / 128), 256, SMEM_MMA>>>(
        CE, CH, CS, sfhi, sflo, wmhi, wmlo, be1, sP);

    // 1c) hidden = relu(U[src] + S + V[dst]) -> fp16 hi/lo (overwrites sf)
    fuse_hidden<<<CE, 256>>>(uvP, sP, src, dst, hidHi, hidLo);

    // 2) e_f = hidden @ We2 + be2             [E, 512]  (overwrites S)
    mma_gemm<false><<<dim3(CD / 256, CE / 128), 256, SMEM_MMA>>>(
        CE, CD, CH, hidHi, hidLo, w2hi, w2lo, be2, efP);

    // 3-5) segment softmax + scatter
    edge_logit_kernel<<<CE / 8, 256>>>(efP, Wa, ba, dst, aP, mP);
    edge_exp_kernel<<<(CE + 255) / 256, 256>>>(aP, dst, mP, exP, denP);
    scatter_z_kernel<<<CE, 128>>>(n_f, efP, src, dst, exP, denP, zfP);

    // 6) new_n = concat(n_f, z_f) @ Wn + bn   [N, 512]  (an overwrites hidden)
    split_node<<<CN_PAD, 256>>>(n_f, zfP, anhi, anlo);
    mma_gemm<false><<<dim3(CD / 256, CN_PAD / 128), 256, SMEM_MMA>>>(
        CN, CD, CH, anhi, anlo, wnhi, wnlo, bn, newnP);

    // 7) ph = relu(concat(new_n[sp], s_f[pe], new_n[dp]) @ Wp1 + bp1)  [P, 512]
    split_pred<<<CP_PAD, 288>>>(newnP, s_f, src, dst, pidx, aphi, aplo);
    mma_gemm<true><<<dim3(CD / 256, CP_PAD / 128), 256, SMEM_MMA>>>(
        CP, CD, K1, aphi, aplo, wphi, wplo, bp1, phP);

    // 8) pred = ph @ Wp2 + bp2
    pred_kernel<<<CP / 8, 256>>>(phP, Wp2, bp2, out);
}

// round 10
// speedup vs baseline: 2.3473x; 1.2460x over previous
#include <cuda_runtime.h>
#include <cuda_fp16.h>
#include <cstdint>

// Problem dimensions (fixed by the dataset)
#define CN 20000
#define CE 160000
#define CP 10000
#define CD 512
#define CS 128
#define CH 1024
#define K1 (2*CD+CS)   // 1152

#define CN_PAD 20096   // 157 * 128
#define CP_PAD 10112   // 79 * 128

// ---------------------------------------------------------------------------
// Static device scratch. Two big pools with lifetime-aliased tenants keep the
// total image under the 2GB small-code-model limit.
// poolA: S [E,1024] f32 (GEMM1b->fuse)  ->  e_f [E,512] f32 (GEMM2->scatter)
// poolB: sf hi (split->GEMM1b) -> hidden hi (fuse->GEMM2)
//        -> an hi/lo + ap hi/lo (node/pred GEMM A operands)
// ---------------------------------------------------------------------------
#define POOLSZ ((size_t)CE * CH * 4)                 // 655,360,000 B
__device__ __align__(1024) char g_poolA[POOLSZ];
__device__ __align__(1024) char g_poolB[POOLSZ];

__device__ __half g_nfhi[(size_t)CN_PAD * CD];       // n_f as fp16 (2-pass A)
__device__ float  g_uv[(size_t)CN_PAD * 2 * CH];     // [N, U(1024) | V(1024)]
__device__ __half g_wuvhi[(size_t)2 * CH * CD];      // [Wtop^T ; Wbot^T]
__device__ __half g_wuvlo[(size_t)2 * CH * CD];
__device__ __half g_wmhi[(size_t)CH * CS];           // Wmid^T  [1024,128]
__device__ __half g_wmlo[(size_t)CH * CS];
__device__ __half g_w2hi[(size_t)CD * CH];           // We2^T   [512,1024]
__device__ __half g_w2lo[(size_t)CD * CH];
__device__ __half g_wnhi[(size_t)CD * CH];           // Wn^T
__device__ __half g_wnlo[(size_t)CD * CH];
__device__ __half g_wphi[(size_t)CD * K1];           // Wp1^T
__device__ __half g_wplo[(size_t)CD * K1];
__device__ float  g_zero[2 * CH];                    // zero bias (zero-init)
__device__ float  g_a[CE];
__device__ float  g_ex[CE];
__device__ float  g_m[CN];
__device__ float  g_den[CN];
__device__ float  g_zf[(size_t)CN * CD];
__device__ float  g_newn[(size_t)CN * CD];
__device__ float  g_ph[(size_t)CP * CD];

// ---------------------------------------------------------------------------
// PTX helpers (all sm_80-class: assemble on plain sm_100)
// ---------------------------------------------------------------------------
__device__ __forceinline__ uint32_t smem_u32(const void* p) {
    uint32_t a;
    asm("{ .reg .u64 t; cvta.to.shared.u64 t, %1; cvt.u32.u64 %0, t; }" : "=r"(a) : "l"(p));
    return a;
}
__device__ __forceinline__ void ldsm_x4(uint32_t* r, uint32_t addr) {
    asm volatile("ldmatrix.sync.aligned.m8n8.x4.shared.b16 {%0,%1,%2,%3}, [%4];"
                 : "=r"(r[0]), "=r"(r[1]), "=r"(r[2]), "=r"(r[3]) : "r"(addr));
}
__device__ __forceinline__ void mma16816(float* d, const uint32_t* a,
                                         const uint32_t b0, const uint32_t b1) {
    asm volatile(
        "mma.sync.aligned.m16n8k16.row.col.f32.f16.f16.f32 "
        "{%0,%1,%2,%3}, {%4,%5,%6,%7}, {%8,%9}, {%0,%1,%2,%3};"
        : "+f"(d[0]), "+f"(d[1]), "+f"(d[2]), "+f"(d[3])
        : "r"(a[0]), "r"(a[1]), "r"(a[2]), "r"(a[3]), "r"(b0), "r"(b1));
}
__device__ __forceinline__ void cp16(uint32_t dst, const void* src) {
    asm volatile("cp.async.cg.shared.global [%0], [%1], 16;"
                 :: "r"(dst), "l"(__cvta_generic_to_global(src)) : "memory");
}
#define CP_COMMIT() asm volatile("cp.async.commit_group;" ::: "memory")
#define CP_WAIT1()  asm volatile("cp.async.wait_group 1;" ::: "memory")

__device__ __forceinline__ uint32_t packh(__half a, __half b) {
    return (uint32_t)__half_as_ushort(a) | ((uint32_t)__half_as_ushort(b) << 16);
}
__device__ __forceinline__ void splitH2(float x0, float x1, uint32_t& hi, uint32_t& lo) {
    __half h0 = __float2half_rn(x0);
    __half h1 = __float2half_rn(x1);
    float r0 = x0 - __half2float(h0);
    float r1 = x1 - __half2float(h1);
    hi = packh(h0, h1);
    lo = packh(__float2half_rn(r0), __float2half_rn(r1));
}

// ---------------------------------------------------------------------------
// Split-fp16 tensor GEMM.  C[M,Ntot] = (relu?)(A @ B^T + bias), fp32 out.
// PASSES==3: A split hi/lo, computes Ah*Bh + Ah*Bl + Al*Bh.
// PASSES==2: A plain fp16 (Alo unused/null), computes Ah*Bh + Ah*Bl.
// A: [Mpad][Ktot] fp16; B: pre-split [Ntot][Ktot] K-major.
// CTA tile 128x256, 256 threads, 8 warps (2m x 4n), warp tile 64x64, BK=32,
// 3-stage cp.async pipeline, XOR-swizzled 64B rows.
// ---------------------------------------------------------------------------
#define AMATB  8192u                     // 128 rows x 64B
#define BMATB  16384u                    // 256 rows x 64B
#define STAGEB 49152u                    // Ah Al Bh Bl
#define SMEM_MMA (3 * STAGEB)

template <bool RELU, int PASSES>
__global__ void __launch_bounds__(256, 1)
mma_gemm(int M, int Ntot, int Ktot,
         const __half* __restrict__ Ahi, const __half* __restrict__ Alo,
         const __half* __restrict__ Bhi, const __half* __restrict__ Blo,
         const float* __restrict__ bias,
         float* __restrict__ outF)
{
    extern __shared__ char smem[];
    const uint32_t sb = smem_u32(smem);

    const int tid  = threadIdx.x;
    const int wid  = tid >> 5, lane = tid & 31;
    const int warpM = wid & 1, warpN = wid >> 1;          // 2 x 4
    const int rowBase = blockIdx.y * 128;
    const int colBase = blockIdx.x * 256;

    const int am = tid >> 1, ah_ = tid & 1;               // A: 2 thr/row
    const uint32_t axor = ((uint32_t)(am >> 1) & 3);
    const uint32_t bxor = ((uint32_t)(tid >> 1) & 3);

    auto cpStage = [&](int st, int c) {
        const int k0 = c << 5;
        const uint32_t base = sb + (uint32_t)st * STAGEB;
        const size_t aOff = (size_t)(rowBase + am) * Ktot + k0 + ah_ * 16;
#pragma unroll
        for (int t = 0; t < 2; t++) {
            const uint32_t d = (uint32_t)am * 64u + (((uint32_t)(ah_ * 2 + t)) ^ axor) * 16u;
            cp16(base + d, Ahi + aOff + t * 8);
            if (PASSES == 3)
                cp16(base + AMATB + d, Alo + aOff + t * 8);
        }
        const size_t bOff = (size_t)(colBase + tid) * Ktot + k0;
#pragma unroll
        for (int q = 0; q < 4; q++) {
            const uint32_t d = (uint32_t)tid * 64u + (((uint32_t)q) ^ bxor) * 16u;
            cp16(base + 2 * AMATB + d,         Bhi + bOff + q * 8);
            cp16(base + 2 * AMATB + BMATB + d, Blo + bOff + q * 8);
        }
    };

    float acc[4][8][4];
#pragma unroll
    for (int a = 0; a < 4; a++)
#pragma unroll
        for (int b = 0; b < 8; b++)
#pragma unroll
            for (int c = 0; c < 4; c++) acc[a][b][c] = 0.f;

    const int NCH = Ktot >> 5;

    cpStage(0, 0); CP_COMMIT();
    cpStage(1, 1); CP_COMMIT();

    const uint32_t xl = ((uint32_t)lane >> 1) & 3u;
    uint32_t lsel[2];
#pragma unroll
    for (int s = 0; s < 2; s++)
        lsel[s] = (uint32_t)(lane & 15) * 64u +
                  ((((uint32_t)s * 2u + ((uint32_t)lane >> 4)) ^ xl) * 16u);

    for (int c = 0; c < NCH; c++) {
        CP_WAIT1();
        __syncthreads();
        if (c + 2 < NCH) cpStage((c + 2) % 3, c + 2);
        CP_COMMIT();

        const uint32_t stb = sb + (uint32_t)(c % 3) * STAGEB;
        const uint32_t aH = stb, aL = stb + AMATB;
        const uint32_t bH = stb + 2 * AMATB, bL = stb + 2 * AMATB + BMATB;

#pragma unroll
        for (int s = 0; s < 2; s++) {
            uint32_t ahf[4][4], alf[4][4], bhf[4][4], blf[4][4];
#pragma unroll
            for (int mt = 0; mt < 4; mt++) {
                const uint32_t ro = (uint32_t)(warpM * 64 + mt * 16) * 64u + lsel[s];
                ldsm_x4(ahf[mt], aH + ro);
                if (PASSES == 3) ldsm_x4(alf[mt], aL + ro);
            }
#pragma unroll
            for (int i = 0; i < 4; i++) {
                const uint32_t ro = (uint32_t)(warpN * 64 + i * 16) * 64u + lsel[s];
                ldsm_x4(bhf[i], bH + ro);
                ldsm_x4(blf[i], bL + ro);
            }
#pragma unroll
            for (int mt = 0; mt < 4; mt++)
#pragma unroll
                for (int nt = 0; nt < 8; nt++)
                    mma16816(acc[mt][nt], ahf[mt], bhf[nt >> 1][nt & 1], bhf[nt >> 1][2 + (nt & 1)]);
#pragma unroll
            for (int mt = 0; mt < 4; mt++)
#pragma unroll
                for (int nt = 0; nt < 8; nt++)
                    mma16816(acc[mt][nt], ahf[mt], blf[nt >> 1][nt & 1], blf[nt >> 1][2 + (nt & 1)]);
            if (PASSES == 3) {
#pragma unroll
                for (int mt = 0; mt < 4; mt++)
#pragma unroll
                    for (int nt = 0; nt < 8; nt++)
                        mma16816(acc[mt][nt], alf[mt], bhf[nt >> 1][nt & 1], bhf[nt >> 1][2 + (nt & 1)]);
            }
        }
    }

    // epilogue (fp32 out)
#pragma unroll
    for (int mt = 0; mt < 4; mt++) {
        const int r0 = rowBase + warpM * 64 + mt * 16 + (lane >> 2);
#pragma unroll
        for (int nt = 0; nt < 8; nt++) {
            const int c0 = colBase + warpN * 64 + nt * 8 + (lane & 3) * 2;
            const float b0 = bias[c0], b1 = bias[c0 + 1];
            float v00 = acc[mt][nt][0] + b0, v01 = acc[mt][nt][1] + b1;
            float v10 = acc[mt][nt][2] + b0, v11 = acc[mt][nt][3] + b1;
            if (RELU) {
                v00 = fmaxf(v00, 0.f); v01 = fmaxf(v01, 0.f);
                v10 = fmaxf(v10, 0.f); v11 = fmaxf(v11, 0.f);
            }
            if (r0 < M)
                *(float2*)(outF + (size_t)r0 * Ntot + c0) = make_float2(v00, v01);
            if (r0 + 8 < M)
                *(float2*)(outF + (size_t)(r0 + 8) * Ntot + c0) = make_float2(v10, v11);
        }
    }
}

// ---------------------------------------------------------------------------
// hidden = relu(U[src[e]] + S[e] + V[dst[e]]) -> fp16 (hi only; 2-pass GEMM2)
// ---------------------------------------------------------------------------
__global__ void fuse_hidden(const float* __restrict__ uv, const float* __restrict__ s,
                            const int* __restrict__ src, const int* __restrict__ dst,
                            __half* __restrict__ hi)
{
    const int e = blockIdx.x;
    const int j = threadIdx.x * 4;                 // 256 threads -> 1024
    const float4 u = *(const float4*)(uv + (size_t)src[e] * 2 * CH + j);
    const float4 v = *(const float4*)(uv + (size_t)dst[e] * 2 * CH + CH + j);
    const float4 sv = *(const float4*)(s + (size_t)e * CH + j);
    float x0 = fmaxf(u.x + v.x + sv.x, 0.f);
    float x1 = fmaxf(u.y + v.y + sv.y, 0.f);
    float x2 = fmaxf(u.z + v.z + sv.z, 0.f);
    float x3 = fmaxf(u.w + v.w + sv.w, 0.f);
    uint32_t h0 = packh(__float2half_rn(x0), __float2half_rn(x1));
    uint32_t h1 = packh(__float2half_rn(x2), __float2half_rn(x3));
    *(uint2*)(hi + (size_t)e * CH + j) = make_uint2(h0, h1);
}

// ---------------------------------------------------------------------------
// A-operand prep kernels
// ---------------------------------------------------------------------------
__global__ void cvt_nf(const float* __restrict__ nf, __half* __restrict__ hi)
{
    const int r = blockIdx.x;                      // 0..CN_PAD-1
    const int rs = r < CN ? r : CN - 1;
    const int j = threadIdx.x * 4;                 // 128 threads -> 512
    float4 v = *(const float4*)(nf + (size_t)rs * CD + j);
    uint32_t h0 = packh(__float2half_rn(v.x), __float2half_rn(v.y));
    uint32_t h1 = packh(__float2half_rn(v.z), __float2half_rn(v.w));
    *(uint2*)(hi + (size_t)r * CD + j) = make_uint2(h0, h1);
}

__global__ void cvt_sf(const float* __restrict__ sf, __half* __restrict__ hi)
{
    const size_t idx = ((size_t)blockIdx.x * 256 + threadIdx.x) * 4;  // over E*128
    float4 v = *(const float4*)(sf + idx);
    uint32_t h0 = packh(__float2half_rn(v.x), __float2half_rn(v.y));
    uint32_t h1 = packh(__float2half_rn(v.z), __float2half_rn(v.w));
    *(uint2*)(hi + idx) = make_uint2(h0, h1);
}

__global__ void split_node(const float* __restrict__ nf, const float* __restrict__ zf,
                           __half* __restrict__ hi, __half* __restrict__ lo)
{
    const int r = blockIdx.x;                  // 0..CN_PAD-1
    const int rs = r < CN ? r : CN - 1;
    const int j = threadIdx.x * 4;             // 256 threads -> 1024
    const float* p = (j < CD) ? (nf + (size_t)rs * CD + j)
                              : (zf + (size_t)rs * CD + (j - CD));
    float4 v = *(const float4*)p;
    uint32_t h0, l0, h1, l1;
    splitH2(v.x, v.y, h0, l0);
    splitH2(v.z, v.w, h1, l1);
    size_t o = (size_t)r * CH + j;
    *(uint2*)(hi + o) = make_uint2(h0, h1);
    *(uint2*)(lo + o) = make_uint2(l0, l1);
}

__global__ void split_pred(const float* __restrict__ newn, const float* __restrict__ sf,
                           const int* __restrict__ src, const int* __restrict__ dst,
                           const int* __restrict__ pidx,
                           __half* __restrict__ hi, __half* __restrict__ lo)
{
    const int r = blockIdx.x;                  // 0..CP_PAD-1
    const int rp = r < CP ? r : CP - 1;
    const int pe = pidx[rp];
    const int j = threadIdx.x * 4;             // 288 threads -> 1152
    const float* p;
    if (j < CD)            p = newn + (size_t)src[pe] * CD + j;
    else if (j < CD + CS)  p = sf + (size_t)pe * CS + (j - CD);
    else                   p = newn + (size_t)dst[pe] * CD + (j - CD - CS);
    float4 v = *(const float4*)p;
    uint32_t h0, l0, h1, l1;
    splitH2(v.x, v.y, h0, l0);
    splitH2(v.z, v.w, h1, l1);
    size_t o = (size_t)r * K1 + j;
    *(uint2*)(hi + o) = make_uint2(h0, h1);
    *(uint2*)(lo + o) = make_uint2(l0, l1);
}

// ---------------------------------------------------------------------------
// Weight prep: out[(outRowOff+n)*Kst + k] = W[(rowOff+kb..)*WN + n], split hi/lo
// ---------------------------------------------------------------------------
__global__ void transpose_split(const float* __restrict__ W, int WN, int rowOff,
                                __half* __restrict__ hi, __half* __restrict__ lo,
                                int outRowOff, int Kst)
{
    __shared__ float t[32][33];
    const int nb = blockIdx.x * 32, kb = blockIdx.y * 32;
    const int x = threadIdx.x, y = threadIdx.y;   // (32,8)
#pragma unroll
    for (int i = 0; i < 32; i += 8)
        t[y + i][x] = W[(size_t)(rowOff + kb + y + i) * WN + nb + x];
    __syncthreads();
#pragma unroll
    for (int i = 0; i < 32; i += 8) {
        float v = t[x][y + i];
        __half h = __float2half_rn(v);
        size_t o = (size_t)(outRowOff + nb + y + i) * Kst + kb + x;
        hi[o] = h;
        lo[o] = __float2half_rn(v - __half2float(h));
    }
}

// ---------------------------------------------------------------------------
// Segment softmax + scatter
// ---------------------------------------------------------------------------
__device__ __forceinline__ void atomicMaxFloat(float* addr, float value) {
    if (value >= 0.f)
        atomicMax((int*)addr, __float_as_int(value));
    else
        atomicMin((unsigned int*)addr, __float_as_uint(value));
}

__global__ void init_kernel(float* __restrict__ m, float* __restrict__ den,
                            float* __restrict__ zf)
{
    size_t i = (size_t)blockIdx.x * 256 + threadIdx.x;
    if (i < (size_t)CN * CD) zf[i] = 0.f;
    if (i < CN) { m[i] = __int_as_float(0xff800000); den[i] = 0.f; }
}

__global__ void edge_logit_kernel(const float* __restrict__ ef,
                                  const float* __restrict__ Wa,
                                  const float* __restrict__ ba,
                                  const int*   __restrict__ dst,
                                  float* __restrict__ a,
                                  float* __restrict__ m)
{
    int e    = blockIdx.x * 8 + (threadIdx.x >> 5);
    int lane = threadIdx.x & 31;
    if (e >= CE) return;
    const float4* row = (const float4*)(ef + (size_t)e * CD);
    const float4* w   = (const float4*)Wa;
    float s = 0.f;
#pragma unroll
    for (int i = 0; i < 4; i++) {
        float4 v  = row[lane + i * 32];
        float4 wv = w[lane + i * 32];
        s += v.x * wv.x + v.y * wv.y + v.z * wv.z + v.w * wv.w;
    }
#pragma unroll
    for (int o = 16; o; o >>= 1) s += __shfl_xor_sync(0xffffffffu, s, o);
    if (lane == 0) {
        s += ba[0];
        a[e] = s;
        atomicMaxFloat(&m[dst[e]], s);
    }
}

__global__ void edge_exp_kernel(const float* __restrict__ a,
                                const int*   __restrict__ dst,
                                const float* __restrict__ m,
                                float* __restrict__ ex,
                                float* __restrict__ den)
{
    int e = blockIdx.x * 256 + threadIdx.x;
    if (e >= CE) return;
    int d = dst[e];
    float v = expf(a[e] - m[d]);
    ex[e] = v;
    atomicAdd(&den[d], v);
}

__global__ void scatter_z_kernel(const float* __restrict__ nf,
                                 const float* __restrict__ ef,
                                 const int*   __restrict__ src,
                                 const int*   __restrict__ dst,
                                 const float* __restrict__ ex,
                                 const float* __restrict__ den,
                                 float* __restrict__ zf)
{
    int e = blockIdx.x;
    int t = threadIdx.x;
    int d = dst[e], s = src[e];
    float alpha = ex[e] / den[d];
    float4 v = *(const float4*)(nf + (size_t)s * CD + t * 4);
    float4 w = *(const float4*)(ef + (size_t)e * CD + t * 4);
    float* zp = zf + (size_t)d * CD + t * 4;
    atomicAdd(zp + 0, alpha * (v.x + w.x));
    atomicAdd(zp + 1, alpha * (v.y + w.y));
    atomicAdd(zp + 2, alpha * (v.z + w.z));
    atomicAdd(zp + 3, alpha * (v.w + w.w));
}

__global__ void pred_kernel(const float* __restrict__ ph,
                            const float* __restrict__ Wp2,
                            const float* __restrict__ bp2,
                            float* __restrict__ out)
{
    int p    = blockIdx.x * 8 + (threadIdx.x >> 5);
    int lane = threadIdx.x & 31;
    if (p >= CP) return;
    const float4* row = (const float4*)(ph + (size_t)p * CD);
    const float4* w   = (const float4*)Wp2;
    float s = 0.f;
#pragma unroll
    for (int i = 0; i < 4; i++) {
        float4 v  = row[lane + i * 32];
        float4 wv = w[lane + i * 32];
        s += v.x * wv.x + v.y * wv.y + v.z * wv.z + v.w * wv.w;
    }
#pragma unroll
    for (int o = 16; o; o >>= 1) s += __shfl_xor_sync(0xffffffffu, s, o);
    if (lane == 0) out[p] = s + bp2[0];
}

// ---------------------------------------------------------------------------
// Launch
// ---------------------------------------------------------------------------
extern "C" void kernel_launch(void* const* d_in, const int* in_sizes, int n_in,
                              void* d_out, int out_size)
{
    const float* n_f  = (const float*)d_in[0];
    const float* s_f  = (const float*)d_in[1];
    const float* We1  = (const float*)d_in[2];
    const float* be1  = (const float*)d_in[3];
    const float* We2  = (const float*)d_in[4];
    const float* be2  = (const float*)d_in[5];
    const float* Wa   = (const float*)d_in[6];
    const float* ba   = (const float*)d_in[7];
    const float* Wn   = (const float*)d_in[8];
    const float* bn   = (const float*)d_in[9];
    const float* Wp1  = (const float*)d_in[10];
    const float* bp1  = (const float*)d_in[11];
    const float* Wp2  = (const float*)d_in[12];
    const float* bp2  = (const float*)d_in[13];
    const int*   src  = (const int*)d_in[14];
    const int*   dst  = (const int*)d_in[15];
    const int*   pidx = (const int*)d_in[16];
    float* out = (float*)d_out;

    char *poolA, *poolB;
    __half *nfhi;
    __half *wuvhi, *wuvlo, *wmhi, *wmlo, *w2hi, *w2lo, *wnhi, *wnlo, *wphi, *wplo;
    float *uvP, *zeroP, *aP, *exP, *mP, *denP, *zfP, *newnP, *phP;
    cudaGetSymbolAddress((void**)&poolA, g_poolA);
    cudaGetSymbolAddress((void**)&poolB, g_poolB);
    cudaGetSymbolAddress((void**)&nfhi,  g_nfhi);
    cudaGetSymbolAddress((void**)&uvP,   g_uv);
    cudaGetSymbolAddress((void**)&wuvhi, g_wuvhi);
    cudaGetSymbolAddress((void**)&wuvlo, g_wuvlo);
    cudaGetSymbolAddress((void**)&wmhi,  g_wmhi);
    cudaGetSymbolAddress((void**)&wmlo,  g_wmlo);
    cudaGetSymbolAddress((void**)&w2hi,  g_w2hi);
    cudaGetSymbolAddress((void**)&w2lo,  g_w2lo);
    cudaGetSymbolAddress((void**)&wnhi,  g_wnhi);
    cudaGetSymbolAddress((void**)&wnlo,  g_wnlo);
    cudaGetSymbolAddress((void**)&wphi,  g_wphi);
    cudaGetSymbolAddress((void**)&wplo,  g_wplo);
    cudaGetSymbolAddress((void**)&zeroP, g_zero);
    cudaGetSymbolAddress((void**)&aP,    g_a);
    cudaGetSymbolAddress((void**)&exP,   g_ex);
    cudaGetSymbolAddress((void**)&mP,    g_m);
    cudaGetSymbolAddress((void**)&denP,  g_den);
    cudaGetSymbolAddress((void**)&zfP,   g_zf);
    cudaGetSymbolAddress((void**)&newnP, g_newn);
    cudaGetSymbolAddress((void**)&phP,   g_ph);

    // --- pool tenants (lifetimes are strictly sequential on the stream) ---
    // poolA: S [E,1024] f32  -> e_f [E,512] f32
    float*  sP    = (float*)poolA;
    float*  efP   = (float*)poolA;
    // poolB phase 1: s_f fp16 (41 MB)
    __half* sfhi  = (__half*)poolB;
    // poolB phase 2: hidden fp16 (327.68 MB; overwrites sf after GEMM1b)
    __half* hidHi = (__half*)poolB;
    // poolB phase 3: node/pred A operands (after GEMM2 consumed hidden)
    __half* anhi  = (__half*)poolB;
    __half* anlo  = (__half*)(poolB + (size_t)CN_PAD * CH * 2);
    __half* aphi  = (__half*)(poolB + (size_t)CN_PAD * CH * 4);
    __half* aplo  = (__half*)(poolB + (size_t)CN_PAD * CH * 4 + (size_t)CP_PAD * K1 * 2);

    cudaFuncSetAttribute(mma_gemm<false, 2>, cudaFuncAttributeMaxDynamicSharedMemorySize, SMEM_MMA);
    cudaFuncSetAttribute(mma_gemm<false, 3>, cudaFuncAttributeMaxDynamicSharedMemorySize, SMEM_MMA);
    cudaFuncSetAttribute(mma_gemm<true, 3>,  cudaFuncAttributeMaxDynamicSharedMemorySize, SMEM_MMA);

    // 0) weight prep:  g_wuv = [Wtop^T ; Wbot^T], g_wm = Wmid^T, plus We2/Wn/Wp1
    transpose_split<<<dim3(CH / 32, CD / 32), dim3(32, 8)>>>(We1, CH, 0,   wuvhi, wuvlo, 0,  CD);
    transpose_split<<<dim3(CH / 32, CD / 32), dim3(32, 8)>>>(We1, CH, 640, wuvhi, wuvlo, CH, CD);
    transpose_split<<<dim3(CH / 32, CS / 32), dim3(32, 8)>>>(We1, CH, 512, wmhi,  wmlo,  0,  CS);
    transpose_split<<<dim3(CD / 32, CH / 32), dim3(32, 8)>>>(We2, CD, 0,   w2hi,  w2lo,  0,  CH);
    transpose_split<<<dim3(CD / 32, CH / 32), dim3(32, 8)>>>(Wn,  CD, 0,   wnhi,  wnlo,  0,  CH);
    transpose_split<<<dim3(CD / 32, K1 / 32), dim3(32, 8)>>>(Wp1, CD, 0,   wphi,  wplo,  0,  K1);
    init_kernel<<<(CN * CD + 255) / 256, 256>>>(mP, denP, zfP);
    cvt_nf<<<CN_PAD, 128>>>(n_f, nfhi);
    cvt_sf<<<(CE * CS / 4) / 256, 256>>>(s_f, sfhi);

    // 1a) [U|V] = n_f @ [Wtop Wbot]           [N, 2048]    (2-pass)
    mma_gemm<false, 2><<<dim3(2 * CH / 256, CN_PAD / 128), 256, SMEM_MMA>>>(
        CN, 2 * CH, CD, nfhi, nullptr, wuvhi, wuvlo, zeroP, uvP);

    // 1b) S = s_f @ Wmid + be1                [E, 1024]    (2-pass)
    mma_gemm<false, 2><<<dim3(CH / 256, CE / 128), 256, SMEM_MMA>>>(
        CE, CH, CS, sfhi, nullptr, wmhi, wmlo, be1, sP);

    // 1c) hidden = relu(U[src] + S + V[dst]) -> fp16 (overwrites sf)
    fuse_hidden<<<CE, 256>>>(uvP, sP, src, dst, hidHi);

    // 2) e_f = hidden @ We2 + be2             [E, 512]     (2-pass; overwrites S)
    mma_gemm<false, 2><<<dim3(CD / 256, CE / 128), 256, SMEM_MMA>>>(
        CE, CD, CH, hidHi, nullptr, w2hi, w2lo, be2, efP);

    // 3-5) segment softmax + scatter
    edge_logit_kernel<<<CE / 8, 256>>>(efP, Wa, ba, dst, aP, mP);
    edge_exp_kernel<<<(CE + 255) / 256, 256>>>(aP, dst, mP, exP, denP);
    scatter_z_kernel<<<CE, 128>>>(n_f, efP, src, dst, exP, denP, zfP);

    // 6) new_n = concat(n_f, z_f) @ Wn + bn   [N, 512]     (3-pass; an overwrites hidden)
    split_node<<<CN_PAD, 256>>>(n_f, zfP, anhi, anlo);
    mma_gemm<false, 3><<<dim3(CD / 256, CN_PAD / 128), 256, SMEM_MMA>>>(
        CN, CD, CH, anhi, anlo, wnhi, wnlo, bn, newnP);

    // 7) ph = relu(concat(new_n[sp], s_f[pe], new_n[dp]) @ Wp1 + bp1)  [P, 512]  (3-pass)
    split_pred<<<CP_PAD, 288>>>(newnP, s_f, src, dst, pidx, aphi, aplo);
    mma_gemm<true, 3><<<dim3(CD / 256, CP_PAD / 128), 256, SMEM_MMA>>>(
        CP, CD, K1, aphi, aplo, wphi, wplo, bp1, phP);

    // 8) pred = ph @ Wp2 + bp2
    pred_kernel<<<CP / 8, 256>>>(phP, Wp2, bp2, out);
}

// round 11
// speedup vs baseline: 3.3272x; 1.4175x over previous
#include <cuda_runtime.h>
#include <cuda_fp16.h>
#include <cstdint>

// Problem dimensions (fixed by the dataset)
#define CN 20000
#define CE 160000
#define CP 10000
#define CD 512
#define CS 128
#define CH 1024
#define K1 (2*CD+CS)   // 1152

#define CN_PAD 20096   // 157 * 128
#define CP_PAD 10112   // 79 * 128

// ---------------------------------------------------------------------------
// Static device scratch. Lifetime-aliased pools keep the image < 2GB.
// poolA: S [E,1024] f32 (GEMM1b -> fuse_hidden)
// poolB: sf fp16 -> hidden fp16 (fuse -> scatter) ; hbar16 at +400MB ;
//        then an/ap hi/lo (node/pred A operands) from offset 0
// g_uv:  U|V [N,2048] f32 (GEMM1a -> fuse) -> hbar f32 [N,1024] (scatter) |
//        zmix [N,512] f32 at +CN_PAD*1024 (zmix GEMM -> split_node)
// ---------------------------------------------------------------------------
#define POOLSZ ((size_t)CE * CH * 4)                 // 655,360,000 B
__device__ __align__(1024) char g_poolA[POOLSZ];
__device__ __align__(1024) char g_poolB[POOLSZ];
#define HB16_OFF ((size_t)400 * 1000 * 1000)

__device__ __half g_nfhi[(size_t)CN_PAD * CD];       // n_f as fp16
__device__ float  g_uv[(size_t)CN_PAD * 2 * CH];
__device__ __half g_wuvhi[(size_t)2 * CH * CD];      // [Wtop^T ; Wbot^T]
__device__ __half g_wuvlo[(size_t)2 * CH * CD];
__device__ __half g_wmhi[(size_t)CH * CS];           // Wmid^T  [1024,128]
__device__ __half g_wmlo[(size_t)CH * CS];
__device__ __half g_w2hi[(size_t)CD * CH];           // We2^T   [512,1024]
__device__ __half g_w2lo[(size_t)CD * CH];
__device__ __half g_wnhi[(size_t)CD * CH];           // Wn^T
__device__ __half g_wnlo[(size_t)CD * CH];
__device__ __half g_wphi[(size_t)CD * K1];           // Wp1^T
__device__ __half g_wplo[(size_t)CD * K1];
__device__ float  g_w2a[CH];                         // We2 @ Wa
__device__ float  g_ba2[1];                          // be2.Wa + ba
__device__ float  g_zero[2 * CH];                    // zero bias (zero-init)
__device__ float  g_a[CE];
__device__ float  g_ex[CE];
__device__ float  g_m[CN];
__device__ float  g_den[CN];
__device__ float  g_zf[(size_t)CN * CD];
__device__ float  g_newn[(size_t)CN * CD];
__device__ float  g_ph[(size_t)CP * CD];

// ---------------------------------------------------------------------------
// PTX helpers (sm_80/sm_90-class; assemble on plain sm_100)
// ---------------------------------------------------------------------------
__device__ __forceinline__ uint32_t smem_u32(const void* p) {
    uint32_t a;
    asm("{ .reg .u64 t; cvta.to.shared.u64 t, %1; cvt.u32.u64 %0, t; }" : "=r"(a) : "l"(p));
    return a;
}
__device__ __forceinline__ void ldsm_x4(uint32_t* r, uint32_t addr) {
    asm volatile("ldmatrix.sync.aligned.m8n8.x4.shared.b16 {%0,%1,%2,%3}, [%4];"
                 : "=r"(r[0]), "=r"(r[1]), "=r"(r[2]), "=r"(r[3]) : "r"(addr));
}
__device__ __forceinline__ void mma16816(float* d, const uint32_t* a,
                                         const uint32_t b0, const uint32_t b1) {
    asm volatile(
        "mma.sync.aligned.m16n8k16.row.col.f32.f16.f16.f32 "
        "{%0,%1,%2,%3}, {%4,%5,%6,%7}, {%8,%9}, {%0,%1,%2,%3};"
        : "+f"(d[0]), "+f"(d[1]), "+f"(d[2]), "+f"(d[3])
        : "r"(a[0]), "r"(a[1]), "r"(a[2]), "r"(a[3]), "r"(b0), "r"(b1));
}
__device__ __forceinline__ void cp16(uint32_t dst, const void* src) {
    asm volatile("cp.async.cg.shared.global [%0], [%1], 16;"
                 :: "r"(dst), "l"(__cvta_generic_to_global(src)) : "memory");
}
#define CP_COMMIT() asm volatile("cp.async.commit_group;" ::: "memory")
#define CP_WAIT1()  asm volatile("cp.async.wait_group 1;" ::: "memory")

// sm_90+ vectorized global reduction (no return value)
__device__ __forceinline__ void red_add_v4(float* addr, float a, float b, float c, float d) {
    asm volatile("red.global.add.v4.f32 [%0], {%1, %2, %3, %4};"
                 :: "l"(__cvta_generic_to_global(addr)), "f"(a), "f"(b), "f"(c), "f"(d)
                 : "memory");
}

__device__ __forceinline__ uint32_t packh(__half a, __half b) {
    return (uint32_t)__half_as_ushort(a) | ((uint32_t)__half_as_ushort(b) << 16);
}
__device__ __forceinline__ void splitH2(float x0, float x1, uint32_t& hi, uint32_t& lo) {
    __half h0 = __float2half_rn(x0);
    __half h1 = __float2half_rn(x1);
    float r0 = x0 - __half2float(h0);
    float r1 = x1 - __half2float(h1);
    hi = packh(h0, h1);
    lo = packh(__float2half_rn(r0), __float2half_rn(r1));
}

// ---------------------------------------------------------------------------
// Split-fp16 tensor GEMM.  C[M,Ntot] = (relu?)(A @ B^T + bias [+ addend]), f32
// PASSES==3: A split hi/lo (Ah*Bh + Ah*Bl + Al*Bh); PASSES==2: A plain fp16.
// ZMIX: C = acc + addend[r][c] + gate01(gate[r]) * bias[c]   (z_f mix epilogue)
// CTA tile 128x256, 256 threads, 8 warps (2m x 4n), BK=32, 3-stage cp.async.
// ---------------------------------------------------------------------------
#define AMATB  8192u
#define BMATB  16384u
#define STAGEB 49152u
#define SMEM_MMA (3 * STAGEB)

template <bool RELU, int PASSES, bool ZMIX>
__global__ void __launch_bounds__(256, 1)
mma_gemm(int M, int Ntot, int Ktot,
         const __half* __restrict__ Ahi, const __half* __restrict__ Alo,
         const __half* __restrict__ Bhi, const __half* __restrict__ Blo,
         const float* __restrict__ bias,
         const float* __restrict__ addend, const float* __restrict__ gate,
         float* __restrict__ outF)
{
    extern __shared__ char smem[];
    const uint32_t sb = smem_u32(smem);

    const int tid  = threadIdx.x;
    const int wid  = tid >> 5, lane = tid & 31;
    const int warpM = wid & 1, warpN = wid >> 1;
    const int rowBase = blockIdx.y * 128;
    const int colBase = blockIdx.x * 256;

    const int am = tid >> 1, ah_ = tid & 1;
    const uint32_t axor = ((uint32_t)(am >> 1) & 3);
    const uint32_t bxor = ((uint32_t)(tid >> 1) & 3);

    auto cpStage = [&](int st, int c) {
        const int k0 = c << 5;
        const uint32_t base = sb + (uint32_t)st * STAGEB;
        const size_t aOff = (size_t)(rowBase + am) * Ktot + k0 + ah_ * 16;
#pragma unroll
        for (int t = 0; t < 2; t++) {
            const uint32_t d = (uint32_t)am * 64u + (((uint32_t)(ah_ * 2 + t)) ^ axor) * 16u;
            cp16(base + d, Ahi + aOff + t * 8);
            if (PASSES == 3)
                cp16(base + AMATB + d, Alo + aOff + t * 8);
        }
        const size_t bOff = (size_t)(colBase + tid) * Ktot + k0;
#pragma unroll
        for (int q = 0; q < 4; q++) {
            const uint32_t d = (uint32_t)tid * 64u + (((uint32_t)q) ^ bxor) * 16u;
            cp16(base + 2 * AMATB + d,         Bhi + bOff + q * 8);
            cp16(base + 2 * AMATB + BMATB + d, Blo + bOff + q * 8);
        }
    };

    float acc[4][8][4];
#pragma unroll
    for (int a = 0; a < 4; a++)
#pragma unroll
        for (int b = 0; b < 8; b++)
#pragma unroll
            for (int c = 0; c < 4; c++) acc[a][b][c] = 0.f;

    const int NCH = Ktot >> 5;

    cpStage(0, 0); CP_COMMIT();
    cpStage(1, 1); CP_COMMIT();

    const uint32_t xl = ((uint32_t)lane >> 1) & 3u;
    uint32_t lsel[2];
#pragma unroll
    for (int s = 0; s < 2; s++)
        lsel[s] = (uint32_t)(lane & 15) * 64u +
                  ((((uint32_t)s * 2u + ((uint32_t)lane >> 4)) ^ xl) * 16u);

    for (int c = 0; c < NCH; c++) {
        CP_WAIT1();
        __syncthreads();
        if (c + 2 < NCH) cpStage((c + 2) % 3, c + 2);
        CP_COMMIT();

        const uint32_t stb = sb + (uint32_t)(c % 3) * STAGEB;
        const uint32_t aH = stb, aL = stb + AMATB;
        const uint32_t bH = stb + 2 * AMATB, bL = stb + 2 * AMATB + BMATB;

#pragma unroll
        for (int s = 0; s < 2; s++) {
            uint32_t ahf[4][4], alf[4][4], bhf[4][4], blf[4][4];
#pragma unroll
            for (int mt = 0; mt < 4; mt++) {
                const uint32_t ro = (uint32_t)(warpM * 64 + mt * 16) * 64u + lsel[s];
                ldsm_x4(ahf[mt], aH + ro);
                if (PASSES == 3) ldsm_x4(alf[mt], aL + ro);
            }
#pragma unroll
            for (int i = 0; i < 4; i++) {
                const uint32_t ro = (uint32_t)(warpN * 64 + i * 16) * 64u + lsel[s];
                ldsm_x4(bhf[i], bH + ro);
                ldsm_x4(blf[i], bL + ro);
            }
#pragma unroll
            for (int mt = 0; mt < 4; mt++)
#pragma unroll
                for (int nt = 0; nt < 8; nt++)
                    mma16816(acc[mt][nt], ahf[mt], bhf[nt >> 1][nt & 1], bhf[nt >> 1][2 + (nt & 1)]);
#pragma unroll
            for (int mt = 0; mt < 4; mt++)
#pragma unroll
                for (int nt = 0; nt < 8; nt++)
                    mma16816(acc[mt][nt], ahf[mt], blf[nt >> 1][nt & 1], blf[nt >> 1][2 + (nt & 1)]);
            if (PASSES == 3) {
#pragma unroll
                for (int mt = 0; mt < 4; mt++)
#pragma unroll
                    for (int nt = 0; nt < 8; nt++)
                        mma16816(acc[mt][nt], alf[mt], bhf[nt >> 1][nt & 1], bhf[nt >> 1][2 + (nt & 1)]);
            }
        }
    }

    // epilogue (fp32 out)
#pragma unroll
    for (int mt = 0; mt < 4; mt++) {
        const int r0 = rowBase + warpM * 64 + mt * 16 + (lane >> 2);
        float g0 = 1.f, g1 = 1.f;
        if (ZMIX) {
            if (r0 < M)     g0 = (gate[r0]     != 0.f) ? 1.f : 0.f;
            if (r0 + 8 < M) g1 = (gate[r0 + 8] != 0.f) ? 1.f : 0.f;
        }
#pragma unroll
        for (int nt = 0; nt < 8; nt++) {
            const int c0 = colBase + warpN * 64 + nt * 8 + (lane & 3) * 2;
            const float b0 = bias[c0], b1 = bias[c0 + 1];
            float v00 = acc[mt][nt][0], v01 = acc[mt][nt][1];
            float v10 = acc[mt][nt][2], v11 = acc[mt][nt][3];
            if (ZMIX) {
                v00 += g0 * b0; v01 += g0 * b1;
                v10 += g1 * b0; v11 += g1 * b1;
                if (r0 < M) {
                    const float2 ad = *(const float2*)(addend + (size_t)r0 * Ntot + c0);
                    v00 += ad.x; v01 += ad.y;
                }
                if (r0 + 8 < M) {
                    const float2 ad = *(const float2*)(addend + (size_t)(r0 + 8) * Ntot + c0);
                    v10 += ad.x; v11 += ad.y;
                }
            } else {
                v00 += b0; v01 += b1; v10 += b0; v11 += b1;
            }
            if (RELU) {
                v00 = fmaxf(v00, 0.f); v01 = fmaxf(v01, 0.f);
                v10 = fmaxf(v10, 0.f); v11 = fmaxf(v11, 0.f);
            }
            if (r0 < M)
                *(float2*)(outF + (size_t)r0 * Ntot + c0) = make_float2(v00, v01);
            if (r0 + 8 < M)
                *(float2*)(outF + (size_t)(r0 + 8) * Ntot + c0) = make_float2(v10, v11);
        }
    }
}

// ---------------------------------------------------------------------------
// hidden = relu(U[src] + S + V[dst]) -> fp16 ; logit a = hidden.w2a + ba2
// (logit computed from fp32 pre-quantization values); atomic segment max.
// ---------------------------------------------------------------------------
__device__ __forceinline__ void atomicMaxFloat(float* addr, float value) {
    if (value >= 0.f)
        atomicMax((int*)addr, __float_as_int(value));
    else
        atomicMin((unsigned int*)addr, __float_as_uint(value));
}

__global__ void fuse_hidden(const float* __restrict__ uv, const float* __restrict__ s,
                            const float* __restrict__ w2a, const float* __restrict__ ba2,
                            const int* __restrict__ src, const int* __restrict__ dst,
                            __half* __restrict__ hid, float* __restrict__ aOut,
                            float* __restrict__ m)
{
    __shared__ float red[8];
    const int e = blockIdx.x;
    const int tid = threadIdx.x;
    const int j = tid * 4;                 // 256 threads -> 1024
    const int d = dst[e];
    const float4 u  = *(const float4*)(uv + (size_t)src[e] * 2 * CH + j);
    const float4 v  = *(const float4*)(uv + (size_t)d * 2 * CH + CH + j);
    const float4 sv = *(const float4*)(s + (size_t)e * CH + j);
    float x0 = fmaxf(u.x + v.x + sv.x, 0.f);
    float x1 = fmaxf(u.y + v.y + sv.y, 0.f);
    float x2 = fmaxf(u.z + v.z + sv.z, 0.f);
    float x3 = fmaxf(u.w + v.w + sv.w, 0.f);
    uint32_t h0 = packh(__float2half_rn(x0), __float2half_rn(x1));
    uint32_t h1 = packh(__float2half_rn(x2), __float2half_rn(x3));
    *(uint2*)(hid + (size_t)e * CH + j) = make_uint2(h0, h1);

    const float4 w = *(const float4*)(w2a + j);
    float part = x0 * w.x + x1 * w.y + x2 * w.z + x3 * w.w;
#pragma unroll
    for (int o = 16; o; o >>= 1) part += __shfl_xor_sync(0xffffffffu, part, o);
    if ((tid & 31) == 0) red[tid >> 5] = part;
    __syncthreads();
    if (tid == 0) {
        float sum = 0.f;
#pragma unroll
        for (int i = 0; i < 8; i++) sum += red[i];
        sum += ba2[0];
        aOut[e] = sum;
        atomicMaxFloat(&m[d], sum);
    }
}

// ---------------------------------------------------------------------------
// scatter: z_f[dst] += alpha * n_f[src] ; hbar[dst] += alpha * hidden[e]
// ---------------------------------------------------------------------------
__global__ void scatter_all(const float* __restrict__ nf, const __half* __restrict__ hid,
                            const int* __restrict__ src, const int* __restrict__ dst,
                            const float* __restrict__ ex, const float* __restrict__ den,
                            float* __restrict__ zf, float* __restrict__ hbar)
{
    const int e = blockIdx.x;
    const int t = threadIdx.x;             // 256
    const int d = dst[e];
    const float alpha = ex[e] / den[d];

    // hbar: 1024 values, 4 per thread
    const int j = t * 4;
    const uint2 hh = *(const uint2*)(hid + (size_t)e * CH + j);
    const float2 f01 = __half22float2(*(const __half2*)&hh.x);
    const float2 f23 = __half22float2(*(const __half2*)&hh.y);
    red_add_v4(hbar + (size_t)d * CH + j,
               alpha * f01.x, alpha * f01.y, alpha * f23.x, alpha * f23.y);

    // z_f: 512 values, threads 0..127
    if (t < 128) {
        const int j2 = t * 4;
        const float4 nv = *(const float4*)(nf + (size_t)src[e] * CD + j2);
        red_add_v4(zf + (size_t)d * CD + j2,
                   alpha * nv.x, alpha * nv.y, alpha * nv.z, alpha * nv.w);
    }
}

// ---------------------------------------------------------------------------
// prep kernels
// ---------------------------------------------------------------------------
__global__ void cvt_nf(const float* __restrict__ nf, __half* __restrict__ hi)
{
    const int r = blockIdx.x;
    const int rs = r < CN ? r : CN - 1;
    const int j = threadIdx.x * 4;                 // 128 threads -> 512
    float4 v = *(const float4*)(nf + (size_t)rs * CD + j);
    uint32_t h0 = packh(__float2half_rn(v.x), __float2half_rn(v.y));
    uint32_t h1 = packh(__float2half_rn(v.z), __float2half_rn(v.w));
    *(uint2*)(hi + (size_t)r * CD + j) = make_uint2(h0, h1);
}

__global__ void cvt_sf(const float* __restrict__ sf, __half* __restrict__ hi)
{
    const size_t idx = ((size_t)blockIdx.x * 256 + threadIdx.x) * 4;
    float4 v = *(const float4*)(sf + idx);
    uint32_t h0 = packh(__float2half_rn(v.x), __float2half_rn(v.y));
    uint32_t h1 = packh(__float2half_rn(v.z), __float2half_rn(v.w));
    *(uint2*)(hi + idx) = make_uint2(h0, h1);
}

__global__ void cvt_hbar(const float* __restrict__ hb, __half* __restrict__ hi)
{
    const int r = blockIdx.x;                      // 0..CN_PAD-1
    const int rs = r < CN ? r : CN - 1;
    const int j = threadIdx.x * 4;                 // 256 threads -> 1024
    float4 v = *(const float4*)(hb + (size_t)rs * CH + j);
    uint32_t h0 = packh(__float2half_rn(v.x), __float2half_rn(v.y));
    uint32_t h1 = packh(__float2half_rn(v.z), __float2half_rn(v.w));
    *(uint2*)(hi + (size_t)r * CH + j) = make_uint2(h0, h1);
}

__global__ void zero_hbar(float* __restrict__ hb)
{
    size_t i = (size_t)blockIdx.x * 256 + threadIdx.x;
    if (i < (size_t)CN * CH) hb[i] = 0.f;
}

__global__ void split_node(const float* __restrict__ nf, const float* __restrict__ zmix,
                           __half* __restrict__ hi, __half* __restrict__ lo)
{
    const int r = blockIdx.x;
    const int rs = r < CN ? r : CN - 1;
    const int j = threadIdx.x * 4;             // 256 threads -> 1024
    const float* p = (j < CD) ? (nf + (size_t)rs * CD + j)
                              : (zmix + (size_t)rs * CD + (j - CD));
    float4 v = *(const float4*)p;
    uint32_t h0, l0, h1, l1;
    splitH2(v.x, v.y, h0, l0);
    splitH2(v.z, v.w, h1, l1);
    size_t o = (size_t)r * CH + j;
    *(uint2*)(hi + o) = make_uint2(h0, h1);
    *(uint2*)(lo + o) = make_uint2(l0, l1);
}

__global__ void split_pred(const float* __restrict__ newn, const float* __restrict__ sf,
                           const int* __restrict__ src, const int* __restrict__ dst,
                           const int* __restrict__ pidx,
                           __half* __restrict__ hi, __half* __restrict__ lo)
{
    const int r = blockIdx.x;
    const int rp = r < CP ? r : CP - 1;
    const int pe = pidx[rp];
    const int j = threadIdx.x * 4;             // 288 threads -> 1152
    const float* p;
    if (j < CD)            p = newn + (size_t)src[pe] * CD + j;
    else if (j < CD + CS)  p = sf + (size_t)pe * CS + (j - CD);
    else                   p = newn + (size_t)dst[pe] * CD + (j - CD - CS);
    float4 v = *(const float4*)p;
    uint32_t h0, l0, h1, l1;
    splitH2(v.x, v.y, h0, l0);
    splitH2(v.z, v.w, h1, l1);
    size_t o = (size_t)r * K1 + j;
    *(uint2*)(hi + o) = make_uint2(h0, h1);
    *(uint2*)(lo + o) = make_uint2(l0, l1);
}

__global__ void transpose_split(const float* __restrict__ W, int WN, int rowOff,
                                __half* __restrict__ hi, __half* __restrict__ lo,
                                int outRowOff, int Kst)
{
    __shared__ float t[32][33];
    const int nb = blockIdx.x * 32, kb = blockIdx.y * 32;
    const int x = threadIdx.x, y = threadIdx.y;   // (32,8)
#pragma unroll
    for (int i = 0; i < 32; i += 8)
        t[y + i][x] = W[(size_t)(rowOff + kb + y + i) * WN + nb + x];
    __syncthreads();
#pragma unroll
    for (int i = 0; i < 32; i += 8) {
        float v = t[x][y + i];
        __half h = __float2half_rn(v);
        size_t o = (size_t)(outRowOff + nb + y + i) * Kst + kb + x;
        hi[o] = h;
        lo[o] = __float2half_rn(v - __half2float(h));
    }
}

// w2a[k] = dot(We2[k,:], Wa) ; one warp per k
__global__ void w2a_kernel(const float* __restrict__ We2, const float* __restrict__ Wa,
                           float* __restrict__ w2a)
{
    const int k = blockIdx.x * 8 + (threadIdx.x >> 5);
    const int lane = threadIdx.x & 31;
    const float4* row = (const float4*)(We2 + (size_t)k * CD);
    const float4* w   = (const float4*)Wa;
    float s = 0.f;
#pragma unroll
    for (int i = 0; i < 4; i++) {
        float4 a = row[lane + i * 32];
        float4 b = w[lane + i * 32];
        s += a.x * b.x + a.y * b.y + a.z * b.z + a.w * b.w;
    }
#pragma unroll
    for (int o = 16; o; o >>= 1) s += __shfl_xor_sync(0xffffffffu, s, o);
    if (lane == 0) w2a[k] = s;
}

// ba2 = dot(be2, Wa) + ba
__global__ void ba2_kernel(const float* __restrict__ be2, const float* __restrict__ Wa,
                           const float* __restrict__ ba, float* __restrict__ ba2)
{
    __shared__ float red[8];
    const int tid = threadIdx.x;               // 256
    float s = 0.f;
#pragma unroll
    for (int i = 0; i < 2; i++) {
        int j = tid + i * 256;
        s += be2[j] * Wa[j];
    }
#pragma unroll
    for (int o = 16; o; o >>= 1) s += __shfl_xor_sync(0xffffffffu, s, o);
    if ((tid & 31) == 0) red[tid >> 5] = s;
    __syncthreads();
    if (tid == 0) {
        float t = 0.f;
#pragma unroll
        for (int i = 0; i < 8; i++) t += red[i];
        ba2[0] = t + ba[0];
    }
}

__global__ void init_kernel(float* __restrict__ m, float* __restrict__ den,
                            float* __restrict__ zf)
{
    size_t i = (size_t)blockIdx.x * 256 + threadIdx.x;
    if (i < (size_t)CN * CD) zf[i] = 0.f;
    if (i < CN) { m[i] = __int_as_float(0xff800000); den[i] = 0.f; }
}

__global__ void edge_exp_kernel(const float* __restrict__ a,
                                const int*   __restrict__ dst,
                                const float* __restrict__ m,
                                float* __restrict__ ex,
                                float* __restrict__ den)
{
    int e = blockIdx.x * 256 + threadIdx.x;
    if (e >= CE) return;
    int d = dst[e];
    float v = expf(a[e] - m[d]);
    ex[e] = v;
    atomicAdd(&den[d], v);
}

__global__ void pred_kernel(const float* __restrict__ ph,
                            const float* __restrict__ Wp2,
                            const float* __restrict__ bp2,
                            float* __restrict__ out)
{
    int p    = blockIdx.x * 8 + (threadIdx.x >> 5);
    int lane = threadIdx.x & 31;
    if (p >= CP) return;
    const float4* row = (const float4*)(ph + (size_t)p * CD);
    const float4* w   = (const float4*)Wp2;
    float s = 0.f;
#pragma unroll
    for (int i = 0; i < 4; i++) {
        float4 v  = row[lane + i * 32];
        float4 wv = w[lane + i * 32];
        s += v.x * wv.x + v.y * wv.y + v.z * wv.z + v.w * wv.w;
    }
#pragma unroll
    for (int o = 16; o; o >>= 1) s += __shfl_xor_sync(0xffffffffu, s, o);
    if (lane == 0) out[p] = s + bp2[0];
}

// ---------------------------------------------------------------------------
// Launch
// ---------------------------------------------------------------------------
extern "C" void kernel_launch(void* const* d_in, const int* in_sizes, int n_in,
                              void* d_out, int out_size)
{
    const float* n_f  = (const float*)d_in[0];
    const float* s_f  = (const float*)d_in[1];
    const float* We1  = (const float*)d_in[2];
    const float* be1  = (const float*)d_in[3];
    const float* We2  = (const float*)d_in[4];
    const float* be2  = (const float*)d_in[5];
    const float* Wa   = (const float*)d_in[6];
    const float* ba   = (const float*)d_in[7];
    const float* Wn   = (const float*)d_in[8];
    const float* bn   = (const float*)d_in[9];
    const float* Wp1  = (const float*)d_in[10];
    const float* bp1  = (const float*)d_in[11];
    const float* Wp2  = (const float*)d_in[12];
    const float* bp2  = (const float*)d_in[13];
    const int*   src  = (const int*)d_in[14];
    const int*   dst  = (const int*)d_in[15];
    const int*   pidx = (const int*)d_in[16];
    float* out = (float*)d_out;

    char *poolA, *poolB;
    __half *nfhi;
    __half *wuvhi, *wuvlo, *wmhi, *wmlo, *w2hi, *w2lo, *wnhi, *wnlo, *wphi, *wplo;
    float *uvP, *zeroP, *w2aP, *ba2P, *aP, *exP, *mP, *denP, *zfP, *newnP, *phP;
    cudaGetSymbolAddress((void**)&poolA, g_poolA);
    cudaGetSymbolAddress((void**)&poolB, g_poolB);
    cudaGetSymbolAddress((void**)&nfhi,  g_nfhi);
    cudaGetSymbolAddress((void**)&uvP,   g_uv);
    cudaGetSymbolAddress((void**)&wuvhi, g_wuvhi);
    cudaGetSymbolAddress((void**)&wuvlo, g_wuvlo);
    cudaGetSymbolAddress((void**)&wmhi,  g_wmhi);
    cudaGetSymbolAddress((void**)&wmlo,  g_wmlo);
    cudaGetSymbolAddress((void**)&w2hi,  g_w2hi);
    cudaGetSymbolAddress((void**)&w2lo,  g_w2lo);
    cudaGetSymbolAddress((void**)&wnhi,  g_wnhi);
    cudaGetSymbolAddress((void**)&wnlo,  g_wnlo);
    cudaGetSymbolAddress((void**)&wphi,  g_wphi);
    cudaGetSymbolAddress((void**)&wplo,  g_wplo);
    cudaGetSymbolAddress((void**)&zeroP, g_zero);
    cudaGetSymbolAddress((void**)&w2aP,  g_w2a);
    cudaGetSymbolAddress((void**)&ba2P,  g_ba2);
    cudaGetSymbolAddress((void**)&aP,    g_a);
    cudaGetSymbolAddress((void**)&exP,   g_ex);
    cudaGetSymbolAddress((void**)&mP,    g_m);
    cudaGetSymbolAddress((void**)&denP,  g_den);
    cudaGetSymbolAddress((void**)&zfP,   g_zf);
    cudaGetSymbolAddress((void**)&newnP, g_newn);
    cudaGetSymbolAddress((void**)&phP,   g_ph);

    // --- pool tenants (lifetimes strictly sequential on the stream) ---
    float*  sP     = (float*)poolA;                       // S [E,1024] f32
    __half* sfhi   = (__half*)poolB;                      // s_f fp16
    __half* hidHi  = (__half*)poolB;                      // hidden fp16 (after sf dead)
    __half* hbar16 = (__half*)(poolB + HB16_OFF);         // hbar fp16 [CN_PAD,1024]
    __half* anhi   = (__half*)poolB;                      // node A (after hidden dead)
    __half* anlo   = (__half*)(poolB + (size_t)CN_PAD * CH * 2);
    __half* aphi   = (__half*)(poolB + (size_t)CN_PAD * CH * 4);
    __half* aplo   = (__half*)(poolB + (size_t)CN_PAD * CH * 4 + (size_t)CP_PAD * K1 * 2);
    // g_uv: U|V f32 -> (after fuse) hbar f32 [CN,1024] | zmix [CN,512]
    float*  hbarP  = uvP;
    float*  zmixP  = uvP + (size_t)CN_PAD * CH;

    cudaFuncSetAttribute(mma_gemm<false, 2, false>, cudaFuncAttributeMaxDynamicSharedMemorySize, SMEM_MMA);
    cudaFuncSetAttribute(mma_gemm<false, 2, true>,  cudaFuncAttributeMaxDynamicSharedMemorySize, SMEM_MMA);
    cudaFuncSetAttribute(mma_gemm<false, 3, false>, cudaFuncAttributeMaxDynamicSharedMemorySize, SMEM_MMA);
    cudaFuncSetAttribute(mma_gemm<true, 3, false>,  cudaFuncAttributeMaxDynamicSharedMemorySize, SMEM_MMA);

    // 0) weight prep + fused-logit weights + init + input converts
    transpose_split<<<dim3(CH / 32, CD / 32), dim3(32, 8)>>>(We1, CH, 0,   wuvhi, wuvlo, 0,  CD);
    transpose_split<<<dim3(CH / 32, CD / 32), dim3(32, 8)>>>(We1, CH, 640, wuvhi, wuvlo, CH, CD);
    transpose_split<<<dim3(CH / 32, CS / 32), dim3(32, 8)>>>(We1, CH, 512, wmhi,  wmlo,  0,  CS);
    transpose_split<<<dim3(CD / 32, CH / 32), dim3(32, 8)>>>(We2, CD, 0,   w2hi,  w2lo,  0,  CH);
    transpose_split<<<dim3(CD / 32, CH / 32), dim3(32, 8)>>>(Wn,  CD, 0,   wnhi,  wnlo,  0,  CH);
    transpose_split<<<dim3(CD / 32, K1 / 32), dim3(32, 8)>>>(Wp1, CD, 0,   wphi,  wplo,  0,  K1);
    w2a_kernel<<<CH / 8, 256>>>(We2, Wa, w2aP);
    ba2_kernel<<<1, 256>>>(be2, Wa, ba, ba2P);
    init_kernel<<<(CN * CD + 255) / 256, 256>>>(mP, denP, zfP);
    cvt_nf<<<CN_PAD, 128>>>(n_f, nfhi);
    cvt_sf<<<(CE * CS / 4) / 256, 256>>>(s_f, sfhi);

    // 1a) [U|V] = n_f @ [Wtop Wbot]           [N, 2048]   (2-pass)
    mma_gemm<false, 2, false><<<dim3(2 * CH / 256, CN_PAD / 128), 256, SMEM_MMA>>>(
        CN, 2 * CH, CD, nfhi, nullptr, wuvhi, wuvlo, zeroP, nullptr, nullptr, uvP);

    // 1b) S = s_f @ Wmid + be1                [E, 1024]   (2-pass)
    mma_gemm<false, 2, false><<<dim3(CH / 256, CE / 128), 256, SMEM_MMA>>>(
        CE, CH, CS, sfhi, nullptr, wmhi, wmlo, be1, nullptr, nullptr, sP);

    // 1c) hidden fp16 + logit a + segment max  (overwrites sf)
    fuse_hidden<<<CE, 256>>>(uvP, sP, w2aP, ba2P, src, dst, hidHi, aP, mP);

    // 2) softmax denominator; zero hbar (U|V now dead)
    zero_hbar<<<(CN * CH + 255) / 256, 256>>>(hbarP);
    edge_exp_kernel<<<(CE + 255) / 256, 256>>>(aP, dst, mP, exP, denP);

    // 3) scatter: zf += alpha*nf[src], hbar += alpha*hidden
    scatter_all<<<CE, 256>>>(n_f, hidHi, src, dst, exP, denP, zfP, hbarP);

    // 4) zmix = hbar @ We2 + gate*be2 + zf    [N, 512]    (2-pass)
    cvt_hbar<<<CN_PAD, 256>>>(hbarP, hbar16);
    mma_gemm<false, 2, true><<<dim3(CD / 256, CN_PAD / 128), 256, SMEM_MMA>>>(
        CN, CD, CH, hbar16, nullptr, w2hi, w2lo, be2, zfP, denP, zmixP);

    // 5) new_n = concat(n_f, zmix) @ Wn + bn  [N, 512]    (3-pass)
    split_node<<<CN_PAD, 256>>>(n_f, zmixP, anhi, anlo);
    mma_gemm<false, 3, false><<<dim3(CD / 256, CN_PAD / 128), 256, SMEM_MMA>>>(
        CN, CD, CH, anhi, anlo, wnhi, wnlo, bn, nullptr, nullptr, newnP);

    // 6) ph = relu(concat(new_n[sp], s_f[pe], new_n[dp]) @ Wp1 + bp1)  (3-pass)
    split_pred<<<CP_PAD, 288>>>(newnP, s_f, src, dst, pidx, aphi, aplo);
    mma_gemm<true, 3, false><<<dim3(CD / 256, CP_PAD / 128), 256, SMEM_MMA>>>(
        CP, CD, K1, aphi, aplo, wphi, wplo, bp1, nullptr, nullptr, phP);

    // 7) pred = ph @ Wp2 + bp2
    pred_kernel<<<CP / 8, 256>>>(phP, Wp2, bp2, out);
}

// round 12
// speedup vs baseline: 3.6636x; 1.1011x over previous
#include <cuda_runtime.h>
#include <cuda_fp16.h>
#include <cstdint>

// Problem dimensions (fixed by the dataset)
#define CN 20000
#define CE 160000
#define CP 10000
#define CD 512
#define CS 128
#define CH 1024
#define K1 (2*CD+CS)   // 1152

#define CN_PAD 20096   // 157 * 128
#define CP_PAD 10112   // 79 * 128

// ---------------------------------------------------------------------------
// Static device scratch. Lifetime-aliased pools keep the image < 2GB.
// poolA: S [E,1024] f32 (GEMM1b -> fuse_hidden)
// poolB: sf fp16 -> hidden fp16 (fuse -> node_reduce) ; hbar16 at +400MB ;
//        then an/ap hi/lo (node/pred A operands) from offset 0
// g_uv:  U|V [N,2048] f32 (GEMM1a -> fuse) -> zmix [N,512] f32 (reuse)
// ---------------------------------------------------------------------------
#define POOLSZ ((size_t)CE * CH * 4)                 // 655,360,000 B
__device__ __align__(1024) char g_poolA[POOLSZ];
__device__ __align__(1024) char g_poolB[POOLSZ];
#define HB16_OFF ((size_t)400 * 1000 * 1000)

__device__ __half g_nfhi[(size_t)CN_PAD * CD];       // n_f as fp16
__device__ float  g_uv[(size_t)CN_PAD * 2 * CH];
__device__ __half g_wuvhi[(size_t)2 * CH * CD];      // [Wtop^T ; Wbot^T]
__device__ __half g_wuvlo[(size_t)2 * CH * CD];
__device__ __half g_wmhi[(size_t)CH * CS];           // Wmid^T  [1024,128]
__device__ __half g_wmlo[(size_t)CH * CS];
__device__ __half g_w2hi[(size_t)CD * CH];           // We2^T   [512,1024]
__device__ __half g_w2lo[(size_t)CD * CH];
__device__ __half g_wnhi[(size_t)CD * CH];           // Wn^T
__device__ __half g_wnlo[(size_t)CD * CH];
__device__ __half g_wphi[(size_t)CD * K1];           // Wp1^T
__device__ __half g_wplo[(size_t)CD * K1];
__device__ float  g_w2a[CH];                         // We2 @ Wa
__device__ float  g_ba2[1];                          // be2.Wa + ba
__device__ float  g_zero[2 * CH];                    // zero bias (zero-init)
__device__ float  g_a[CE];
__device__ float  g_ex[CE];
__device__ float  g_m[CN];
__device__ float  g_den[CN];
__device__ float  g_zf[(size_t)CN * CD];
__device__ float  g_newn[(size_t)CN * CD];
__device__ float  g_ph[(size_t)CP * CD];
// CSR by dst
__device__ int    g_deg[CN];
__device__ int    g_offs[CN + 1];
__device__ int    g_cursor[CN];
__device__ int    g_elist[CE];

// ---------------------------------------------------------------------------
// PTX helpers (sm_80-class; assemble on plain sm_100)
// ---------------------------------------------------------------------------
__device__ __forceinline__ uint32_t smem_u32(const void* p) {
    uint32_t a;
    asm("{ .reg .u64 t; cvta.to.shared.u64 t, %1; cvt.u32.u64 %0, t; }" : "=r"(a) : "l"(p));
    return a;
}
__device__ __forceinline__ void ldsm_x4(uint32_t* r, uint32_t addr) {
    asm volatile("ldmatrix.sync.aligned.m8n8.x4.shared.b16 {%0,%1,%2,%3}, [%4];"
                 : "=r"(r[0]), "=r"(r[1]), "=r"(r[2]), "=r"(r[3]) : "r"(addr));
}
__device__ __forceinline__ void mma16816(float* d, const uint32_t* a,
                                         const uint32_t b0, const uint32_t b1) {
    asm volatile(
        "mma.sync.aligned.m16n8k16.row.col.f32.f16.f16.f32 "
        "{%0,%1,%2,%3}, {%4,%5,%6,%7}, {%8,%9}, {%0,%1,%2,%3};"
        : "+f"(d[0]), "+f"(d[1]), "+f"(d[2]), "+f"(d[3])
        : "r"(a[0]), "r"(a[1]), "r"(a[2]), "r"(a[3]), "r"(b0), "r"(b1));
}
__device__ __forceinline__ void cp16(uint32_t dst, const void* src) {
    asm volatile("cp.async.cg.shared.global [%0], [%1], 16;"
                 :: "r"(dst), "l"(__cvta_generic_to_global(src)) : "memory");
}
#define CP_COMMIT() asm volatile("cp.async.commit_group;" ::: "memory")
#define CP_WAIT1()  asm volatile("cp.async.wait_group 1;" ::: "memory")

__device__ __forceinline__ uint32_t packh(__half a, __half b) {
    return (uint32_t)__half_as_ushort(a) | ((uint32_t)__half_as_ushort(b) << 16);
}
__device__ __forceinline__ void splitH2(float x0, float x1, uint32_t& hi, uint32_t& lo) {
    __half h0 = __float2half_rn(x0);
    __half h1 = __float2half_rn(x1);
    float r0 = x0 - __half2float(h0);
    float r1 = x1 - __half2float(h1);
    hi = packh(h0, h1);
    lo = packh(__float2half_rn(r0), __float2half_rn(r1));
}

// ---------------------------------------------------------------------------
// Split-fp16 tensor GEMM.  C[M,Ntot] = (relu?)(A @ B^T + bias [+ addend]), f32
// PASSES==3: A split hi/lo (Ah*Bh + Ah*Bl + Al*Bh); PASSES==2: A plain fp16.
// ZMIX: C = acc + addend[r][c] + gate01(gate[r]) * bias[c]
// CTA tile 128x256, 256 threads, 8 warps (2m x 4n), BK=32, 3-stage cp.async.
// ---------------------------------------------------------------------------
#define AMATB  8192u
#define BMATB  16384u
#define STAGEB 49152u
#define SMEM_MMA (3 * STAGEB)

template <bool RELU, int PASSES, bool ZMIX>
__global__ void __launch_bounds__(256, 1)
mma_gemm(int M, int Ntot, int Ktot,
         const __half* __restrict__ Ahi, const __half* __restrict__ Alo,
         const __half* __restrict__ Bhi, const __half* __restrict__ Blo,
         const float* __restrict__ bias,
         const float* __restrict__ addend, const float* __restrict__ gate,
         float* __restrict__ outF)
{
    extern __shared__ char smem[];
    const uint32_t sb = smem_u32(smem);

    const int tid  = threadIdx.x;
    const int wid  = tid >> 5, lane = tid & 31;
    const int warpM = wid & 1, warpN = wid >> 1;
    const int rowBase = blockIdx.y * 128;
    const int colBase = blockIdx.x * 256;

    const int am = tid >> 1, ah_ = tid & 1;
    const uint32_t axor = ((uint32_t)(am >> 1) & 3);
    const uint32_t bxor = ((uint32_t)(tid >> 1) & 3);

    auto cpStage = [&](int st, int c) {
        const int k0 = c << 5;
        const uint32_t base = sb + (uint32_t)st * STAGEB;
        const size_t aOff = (size_t)(rowBase + am) * Ktot + k0 + ah_ * 16;
#pragma unroll
        for (int t = 0; t < 2; t++) {
            const uint32_t d = (uint32_t)am * 64u + (((uint32_t)(ah_ * 2 + t)) ^ axor) * 16u;
            cp16(base + d, Ahi + aOff + t * 8);
            if (PASSES == 3)
                cp16(base + AMATB + d, Alo + aOff + t * 8);
        }
        const size_t bOff = (size_t)(colBase + tid) * Ktot + k0;
#pragma unroll
        for (int q = 0; q < 4; q++) {
            const uint32_t d = (uint32_t)tid * 64u + (((uint32_t)q) ^ bxor) * 16u;
            cp16(base + 2 * AMATB + d,         Bhi + bOff + q * 8);
            cp16(base + 2 * AMATB + BMATB + d, Blo + bOff + q * 8);
        }
    };

    float acc[4][8][4];
#pragma unroll
    for (int a = 0; a < 4; a++)
#pragma unroll
        for (int b = 0; b < 8; b++)
#pragma unroll
            for (int c = 0; c < 4; c++) acc[a][b][c] = 0.f;

    const int NCH = Ktot >> 5;

    cpStage(0, 0); CP_COMMIT();
    cpStage(1, 1); CP_COMMIT();

    const uint32_t xl = ((uint32_t)lane >> 1) & 3u;
    uint32_t lsel[2];
#pragma unroll
    for (int s = 0; s < 2; s++)
        lsel[s] = (uint32_t)(lane & 15) * 64u +
                  ((((uint32_t)s * 2u + ((uint32_t)lane >> 4)) ^ xl) * 16u);

    for (int c = 0; c < NCH; c++) {
        CP_WAIT1();
        __syncthreads();
        if (c + 2 < NCH) cpStage((c + 2) % 3, c + 2);
        CP_COMMIT();

        const uint32_t stb = sb + (uint32_t)(c % 3) * STAGEB;
        const uint32_t aH = stb, aL = stb + AMATB;
        const uint32_t bH = stb + 2 * AMATB, bL = stb + 2 * AMATB + BMATB;

#pragma unroll
        for (int s = 0; s < 2; s++) {
            uint32_t ahf[4][4], alf[4][4], bhf[4][4], blf[4][4];
#pragma unroll
            for (int mt = 0; mt < 4; mt++) {
                const uint32_t ro = (uint32_t)(warpM * 64 + mt * 16) * 64u + lsel[s];
                ldsm_x4(ahf[mt], aH + ro);
                if (PASSES == 3) ldsm_x4(alf[mt], aL + ro);
            }
#pragma unroll
            for (int i = 0; i < 4; i++) {
                const uint32_t ro = (uint32_t)(warpN * 64 + i * 16) * 64u + lsel[s];
                ldsm_x4(bhf[i], bH + ro);
                ldsm_x4(blf[i], bL + ro);
            }
#pragma unroll
            for (int mt = 0; mt < 4; mt++)
#pragma unroll
                for (int nt = 0; nt < 8; nt++)
                    mma16816(acc[mt][nt], ahf[mt], bhf[nt >> 1][nt & 1], bhf[nt >> 1][2 + (nt & 1)]);
#pragma unroll
            for (int mt = 0; mt < 4; mt++)
#pragma unroll
                for (int nt = 0; nt < 8; nt++)
                    mma16816(acc[mt][nt], ahf[mt], blf[nt >> 1][nt & 1], blf[nt >> 1][2 + (nt & 1)]);
            if (PASSES == 3) {
#pragma unroll
                for (int mt = 0; mt < 4; mt++)
#pragma unroll
                    for (int nt = 0; nt < 8; nt++)
                        mma16816(acc[mt][nt], alf[mt], bhf[nt >> 1][nt & 1], bhf[nt >> 1][2 + (nt & 1)]);
            }
        }
    }

    // epilogue (fp32 out)
#pragma unroll
    for (int mt = 0; mt < 4; mt++) {
        const int r0 = rowBase + warpM * 64 + mt * 16 + (lane >> 2);
        float g0 = 1.f, g1 = 1.f;
        if (ZMIX) {
            if (r0 < M)     g0 = (gate[r0]     != 0.f) ? 1.f : 0.f;
            if (r0 + 8 < M) g1 = (gate[r0 + 8] != 0.f) ? 1.f : 0.f;
        }
#pragma unroll
        for (int nt = 0; nt < 8; nt++) {
            const int c0 = colBase + warpN * 64 + nt * 8 + (lane & 3) * 2;
            const float b0 = bias[c0], b1 = bias[c0 + 1];
            float v00 = acc[mt][nt][0], v01 = acc[mt][nt][1];
            float v10 = acc[mt][nt][2], v11 = acc[mt][nt][3];
            if (ZMIX) {
                v00 += g0 * b0; v01 += g0 * b1;
                v10 += g1 * b0; v11 += g1 * b1;
                if (r0 < M) {
                    const float2 ad = *(const float2*)(addend + (size_t)r0 * Ntot + c0);
                    v00 += ad.x; v01 += ad.y;
                }
                if (r0 + 8 < M) {
                    const float2 ad = *(const float2*)(addend + (size_t)(r0 + 8) * Ntot + c0);
                    v10 += ad.x; v11 += ad.y;
                }
            } else {
                v00 += b0; v01 += b1; v10 += b0; v11 += b1;
            }
            if (RELU) {
                v00 = fmaxf(v00, 0.f); v01 = fmaxf(v01, 0.f);
                v10 = fmaxf(v10, 0.f); v11 = fmaxf(v11, 0.f);
            }
            if (r0 < M)
                *(float2*)(outF + (size_t)r0 * Ntot + c0) = make_float2(v00, v01);
            if (r0 + 8 < M)
                *(float2*)(outF + (size_t)(r0 + 8) * Ntot + c0) = make_float2(v10, v11);
        }
    }
}

// ---------------------------------------------------------------------------
// hidden = relu(U[src] + S + V[dst]) -> fp16 ; logit a = hidden.w2a + ba2
// ---------------------------------------------------------------------------
__device__ __forceinline__ void atomicMaxFloat(float* addr, float value) {
    if (value >= 0.f)
        atomicMax((int*)addr, __float_as_int(value));
    else
        atomicMin((unsigned int*)addr, __float_as_uint(value));
}

__global__ void fuse_hidden(const float* __restrict__ uv, const float* __restrict__ s,
                            const float* __restrict__ w2a, const float* __restrict__ ba2,
                            const int* __restrict__ src, const int* __restrict__ dst,
                            __half* __restrict__ hid, float* __restrict__ aOut,
                            float* __restrict__ m)
{
    __shared__ float red[8];
    const int e = blockIdx.x;
    const int tid = threadIdx.x;
    const int j = tid * 4;                 // 256 threads -> 1024
    const int d = dst[e];
    const float4 u  = *(const float4*)(uv + (size_t)src[e] * 2 * CH + j);
    const float4 v  = *(const float4*)(uv + (size_t)d * 2 * CH + CH + j);
    const float4 sv = *(const float4*)(s + (size_t)e * CH + j);
    float x0 = fmaxf(u.x + v.x + sv.x, 0.f);
    float x1 = fmaxf(u.y + v.y + sv.y, 0.f);
    float x2 = fmaxf(u.z + v.z + sv.z, 0.f);
    float x3 = fmaxf(u.w + v.w + sv.w, 0.f);
    uint32_t h0 = packh(__float2half_rn(x0), __float2half_rn(x1));
    uint32_t h1 = packh(__float2half_rn(x2), __float2half_rn(x3));
    *(uint2*)(hid + (size_t)e * CH + j) = make_uint2(h0, h1);

    const float4 w = *(const float4*)(w2a + j);
    float part = x0 * w.x + x1 * w.y + x2 * w.z + x3 * w.w;
#pragma unroll
    for (int o = 16; o; o >>= 1) part += __shfl_xor_sync(0xffffffffu, part, o);
    if ((tid & 31) == 0) red[tid >> 5] = part;
    __syncthreads();
    if (tid == 0) {
        float sum = 0.f;
#pragma unroll
        for (int i = 0; i < 8; i++) sum += red[i];
        sum += ba2[0];
        aOut[e] = sum;
        atomicMaxFloat(&m[d], sum);
    }
}

// ---------------------------------------------------------------------------
// CSR build (by dst): count -> scan -> fill
// ---------------------------------------------------------------------------
__global__ void count_kernel(const int* __restrict__ dst, int* __restrict__ deg)
{
    int e = blockIdx.x * 256 + threadIdx.x;
    if (e < CE) atomicAdd(&deg[dst[e]], 1);
}

__global__ void scan_kernel(const int* __restrict__ deg, int* __restrict__ offs,
                            int* __restrict__ cursor)
{
    __shared__ int part[1024];
    const int t = threadIdx.x;                 // 1024 threads
    const int CHK = (CN + 1023) / 1024;        // 20
    int s = 0;
#pragma unroll
    for (int i = 0; i < CHK; i++) {
        int idx = t * CHK + i;
        if (idx < CN) s += deg[idx];
    }
    part[t] = s;
    __syncthreads();
    // Hillis-Steele inclusive scan
    for (int o = 1; o < 1024; o <<= 1) {
        int v = (t >= o) ? part[t - o] : 0;
        __syncthreads();
        part[t] += v;
        __syncthreads();
    }
    int off = (t > 0) ? part[t - 1] : 0;       // exclusive base
#pragma unroll
    for (int i = 0; i < CHK; i++) {
        int idx = t * CHK + i;
        if (idx < CN) {
            offs[idx] = off;
            cursor[idx] = off;
            off += deg[idx];
        }
    }
    if (t == 0) offs[CN] = part[1023];
}

__global__ void fill_kernel(const int* __restrict__ dst, int* __restrict__ cursor,
                            int* __restrict__ elist)
{
    int e = blockIdx.x * 256 + threadIdx.x;
    if (e < CE) {
        int pos = atomicAdd(&cursor[dst[e]], 1);
        elist[pos] = e;
    }
}

// ---------------------------------------------------------------------------
// node_reduce: per node n, hbar16[n] = sum_e alpha*hidden[e] (fp16 out),
//              zf[n] = sum_e alpha*n_f[src[e]]. One 256-thread block per node.
// ---------------------------------------------------------------------------
__global__ void node_reduce(const int* __restrict__ offs, const int* __restrict__ elist,
                            const int* __restrict__ src, const float* __restrict__ ex,
                            const float* __restrict__ den,
                            const __half* __restrict__ hid, const float* __restrict__ nf,
                            __half* __restrict__ hbar16, float* __restrict__ zf)
{
    const int n = blockIdx.x;
    const int t = threadIdx.x;             // 256
    const int start = offs[n], end = offs[n + 1];
    const float dn = den[n];
    const float dinv = (end > start && dn != 0.f) ? 1.f / dn : 0.f;

    float h0 = 0.f, h1 = 0.f, h2 = 0.f, h3 = 0.f;   // hbar: 4 cols/thread
    float z0 = 0.f, z1 = 0.f;                        // zf:   2 cols/thread

    for (int i = start; i < end; i++) {
        const int e = elist[i];
        const float alpha = ex[e] * dinv;
        const uint2 hh = *(const uint2*)(hid + (size_t)e * CH + t * 4);
        const float2 f01 = __half22float2(*(const __half2*)&hh.x);
        const float2 f23 = __half22float2(*(const __half2*)&hh.y);
        h0 += alpha * f01.x; h1 += alpha * f01.y;
        h2 += alpha * f23.x; h3 += alpha * f23.y;
        const float2 nv = *(const float2*)(nf + (size_t)src[e] * CD + t * 2);
        z0 += alpha * nv.x; z1 += alpha * nv.y;
    }
    uint32_t p0 = packh(__float2half_rn(h0), __float2half_rn(h1));
    uint32_t p1 = packh(__float2half_rn(h2), __float2half_rn(h3));
    *(uint2*)(hbar16 + (size_t)n * CH + t * 4) = make_uint2(p0, p1);
    *(float2*)(zf + (size_t)n * CD + t * 2) = make_float2(z0, z1);
}

// ---------------------------------------------------------------------------
// prep kernels
// ---------------------------------------------------------------------------
__global__ void cvt_nf(const float* __restrict__ nf, __half* __restrict__ hi)
{
    const int r = blockIdx.x;
    const int rs = r < CN ? r : CN - 1;
    const int j = threadIdx.x * 4;
    float4 v = *(const float4*)(nf + (size_t)rs * CD + j);
    uint32_t h0 = packh(__float2half_rn(v.x), __float2half_rn(v.y));
    uint32_t h1 = packh(__float2half_rn(v.z), __float2half_rn(v.w));
    *(uint2*)(hi + (size_t)r * CD + j) = make_uint2(h0, h1);
}

__global__ void cvt_sf(const float* __restrict__ sf, __half* __restrict__ hi)
{
    const size_t idx = ((size_t)blockIdx.x * 256 + threadIdx.x) * 4;
    float4 v = *(const float4*)(sf + idx);
    uint32_t h0 = packh(__float2half_rn(v.x), __float2half_rn(v.y));
    uint32_t h1 = packh(__float2half_rn(v.z), __float2half_rn(v.w));
    *(uint2*)(hi + idx) = make_uint2(h0, h1);
}

__global__ void split_node(const float* __restrict__ nf, const float* __restrict__ zmix,
                           __half* __restrict__ hi, __half* __restrict__ lo)
{
    const int r = blockIdx.x;
    const int rs = r < CN ? r : CN - 1;
    const int j = threadIdx.x * 4;
    const float* p = (j < CD) ? (nf + (size_t)rs * CD + j)
                              : (zmix + (size_t)rs * CD + (j - CD));
    float4 v = *(const float4*)p;
    uint32_t h0, l0, h1, l1;
    splitH2(v.x, v.y, h0, l0);
    splitH2(v.z, v.w, h1, l1);
    size_t o = (size_t)r * CH + j;
    *(uint2*)(hi + o) = make_uint2(h0, h1);
    *(uint2*)(lo + o) = make_uint2(l0, l1);
}

__global__ void split_pred(const float* __restrict__ newn, const float* __restrict__ sf,
                           const int* __restrict__ src, const int* __restrict__ dst,
                           const int* __restrict__ pidx,
                           __half* __restrict__ hi, __half* __restrict__ lo)
{
    const int r = blockIdx.x;
    const int rp = r < CP ? r : CP - 1;
    const int pe = pidx[rp];
    const int j = threadIdx.x * 4;
    const float* p;
    if (j < CD)            p = newn + (size_t)src[pe] * CD + j;
    else if (j < CD + CS)  p = sf + (size_t)pe * CS + (j - CD);
    else                   p = newn + (size_t)dst[pe] * CD + (j - CD - CS);
    float4 v = *(const float4*)p;
    uint32_t h0, l0, h1, l1;
    splitH2(v.x, v.y, h0, l0);
    splitH2(v.z, v.w, h1, l1);
    size_t o = (size_t)r * K1 + j;
    *(uint2*)(hi + o) = make_uint2(h0, h1);
    *(uint2*)(lo + o) = make_uint2(l0, l1);
}

__global__ void transpose_split(const float* __restrict__ W, int WN, int rowOff,
                                __half* __restrict__ hi, __half* __restrict__ lo,
                                int outRowOff, int Kst)
{
    __shared__ float t[32][33];
    const int nb = blockIdx.x * 32, kb = blockIdx.y * 32;
    const int x = threadIdx.x, y = threadIdx.y;
#pragma unroll
    for (int i = 0; i < 32; i += 8)
        t[y + i][x] = W[(size_t)(rowOff + kb + y + i) * WN + nb + x];
    __syncthreads();
#pragma unroll
    for (int i = 0; i < 32; i += 8) {
        float v = t[x][y + i];
        __half h = __float2half_rn(v);
        size_t o = (size_t)(outRowOff + nb + y + i) * Kst + kb + x;
        hi[o] = h;
        lo[o] = __float2half_rn(v - __half2float(h));
    }
}

__global__ void w2a_kernel(const float* __restrict__ We2, const float* __restrict__ Wa,
                           float* __restrict__ w2a)
{
    const int k = blockIdx.x * 8 + (threadIdx.x >> 5);
    const int lane = threadIdx.x & 31;
    const float4* row = (const float4*)(We2 + (size_t)k * CD);
    const float4* w   = (const float4*)Wa;
    float s = 0.f;
#pragma unroll
    for (int i = 0; i < 4; i++) {
        float4 a = row[lane + i * 32];
        float4 b = w[lane + i * 32];
        s += a.x * b.x + a.y * b.y + a.z * b.z + a.w * b.w;
    }
#pragma unroll
    for (int o = 16; o; o >>= 1) s += __shfl_xor_sync(0xffffffffu, s, o);
    if (lane == 0) w2a[k] = s;
}

__global__ void ba2_kernel(const float* __restrict__ be2, const float* __restrict__ Wa,
                           const float* __restrict__ ba, float* __restrict__ ba2)
{
    __shared__ float red[8];
    const int tid = threadIdx.x;
    float s = 0.f;
#pragma unroll
    for (int i = 0; i < 2; i++) {
        int j = tid + i * 256;
        s += be2[j] * Wa[j];
    }
#pragma unroll
    for (int o = 16; o; o >>= 1) s += __shfl_xor_sync(0xffffffffu, s, o);
    if ((tid & 31) == 0) red[tid >> 5] = s;
    __syncthreads();
    if (tid == 0) {
        float t = 0.f;
#pragma unroll
        for (int i = 0; i < 8; i++) t += red[i];
        ba2[0] = t + ba[0];
    }
}

__global__ void init_kernel(float* __restrict__ m, float* __restrict__ den,
                            int* __restrict__ deg)
{
    int i = blockIdx.x * 256 + threadIdx.x;
    if (i < CN) {
        m[i] = __int_as_float(0xff800000);
        den[i] = 0.f;
        deg[i] = 0;
    }
}

__global__ void edge_exp_kernel(const float* __restrict__ a,
                                const int*   __restrict__ dst,
                                const float* __restrict__ m,
                                float* __restrict__ ex,
                                float* __restrict__ den)
{
    int e = blockIdx.x * 256 + threadIdx.x;
    if (e >= CE) return;
    int d = dst[e];
    float v = expf(a[e] - m[d]);
    ex[e] = v;
    atomicAdd(&den[d], v);
}

__global__ void pred_kernel(const float* __restrict__ ph,
                            const float* __restrict__ Wp2,
                            const float* __restrict__ bp2,
                            float* __restrict__ out)
{
    int p    = blockIdx.x * 8 + (threadIdx.x >> 5);
    int lane = threadIdx.x & 31;
    if (p >= CP) return;
    const float4* row = (const float4*)(ph + (size_t)p * CD);
    const float4* w   = (const float4*)Wp2;
    float s = 0.f;
#pragma unroll
    for (int i = 0; i < 4; i++) {
        float4 v  = row[lane + i * 32];
        float4 wv = w[lane + i * 32];
        s += v.x * wv.x + v.y * wv.y + v.z * wv.z + v.w * wv.w;
    }
#pragma unroll
    for (int o = 16; o; o >>= 1) s += __shfl_xor_sync(0xffffffffu, s, o);
    if (lane == 0) out[p] = s + bp2[0];
}

// ---------------------------------------------------------------------------
// Launch
// ---------------------------------------------------------------------------
extern "C" void kernel_launch(void* const* d_in, const int* in_sizes, int n_in,
                              void* d_out, int out_size)
{
    const float* n_f  = (const float*)d_in[0];
    const float* s_f  = (const float*)d_in[1];
    const float* We1  = (const float*)d_in[2];
    const float* be1  = (const float*)d_in[3];
    const float* We2  = (const float*)d_in[4];
    const float* be2  = (const float*)d_in[5];
    const float* Wa   = (const float*)d_in[6];
    const float* ba   = (const float*)d_in[7];
    const float* Wn   = (const float*)d_in[8];
    const float* bn   = (const float*)d_in[9];
    const float* Wp1  = (const float*)d_in[10];
    const float* bp1  = (const float*)d_in[11];
    const float* Wp2  = (const float*)d_in[12];
    const float* bp2  = (const float*)d_in[13];
    const int*   src  = (const int*)d_in[14];
    const int*   dst  = (const int*)d_in[15];
    const int*   pidx = (const int*)d_in[16];
    float* out = (float*)d_out;

    char *poolA, *poolB;
    __half *nfhi;
    __half *wuvhi, *wuvlo, *wmhi, *wmlo, *w2hi, *w2lo, *wnhi, *wnlo, *wphi, *wplo;
    float *uvP, *zeroP, *w2aP, *ba2P, *aP, *exP, *mP, *denP, *zfP, *newnP, *phP;
    int *degP, *offsP, *cursorP, *elistP;
    cudaGetSymbolAddress((void**)&poolA, g_poolA);
    cudaGetSymbolAddress((void**)&poolB, g_poolB);
    cudaGetSymbolAddress((void**)&nfhi,  g_nfhi);
    cudaGetSymbolAddress((void**)&uvP,   g_uv);
    cudaGetSymbolAddress((void**)&wuvhi, g_wuvhi);
    cudaGetSymbolAddress((void**)&wuvlo, g_wuvlo);
    cudaGetSymbolAddress((void**)&wmhi,  g_wmhi);
    cudaGetSymbolAddress((void**)&wmlo,  g_wmlo);
    cudaGetSymbolAddress((void**)&w2hi,  g_w2hi);
    cudaGetSymbolAddress((void**)&w2lo,  g_w2lo);
    cudaGetSymbolAddress((void**)&wnhi,  g_wnhi);
    cudaGetSymbolAddress((void**)&wnlo,  g_wnlo);
    cudaGetSymbolAddress((void**)&wphi,  g_wphi);
    cudaGetSymbolAddress((void**)&wplo,  g_wplo);
    cudaGetSymbolAddress((void**)&zeroP, g_zero);
    cudaGetSymbolAddress((void**)&w2aP,  g_w2a);
    cudaGetSymbolAddress((void**)&ba2P,  g_ba2);
    cudaGetSymbolAddress((void**)&aP,    g_a);
    cudaGetSymbolAddress((void**)&exP,   g_ex);
    cudaGetSymbolAddress((void**)&mP,    g_m);
    cudaGetSymbolAddress((void**)&denP,  g_den);
    cudaGetSymbolAddress((void**)&zfP,   g_zf);
    cudaGetSymbolAddress((void**)&newnP, g_newn);
    cudaGetSymbolAddress((void**)&phP,   g_ph);
    cudaGetSymbolAddress((void**)&degP,    g_deg);
    cudaGetSymbolAddress((void**)&offsP,   g_offs);
    cudaGetSymbolAddress((void**)&cursorP, g_cursor);
    cudaGetSymbolAddress((void**)&elistP,  g_elist);

    // --- pool tenants (lifetimes strictly sequential on the stream) ---
    float*  sP     = (float*)poolA;                       // S [E,1024] f32
    __half* sfhi   = (__half*)poolB;                      // s_f fp16
    __half* hidHi  = (__half*)poolB;                      // hidden fp16 (after sf dead)
    __half* hbar16 = (__half*)(poolB + HB16_OFF);         // hbar fp16 [CN_PAD,1024]
    __half* anhi   = (__half*)poolB;                      // node A (after hidden dead)
    __half* anlo   = (__half*)(poolB + (size_t)CN_PAD * CH * 2);
    __half* aphi   = (__half*)(poolB + (size_t)CN_PAD * CH * 4);
    __half* aplo   = (__half*)(poolB + (size_t)CN_PAD * CH * 4 + (size_t)CP_PAD * K1 * 2);
    // g_uv: U|V f32 -> (after fuse) zmix [CN,512] at offset CN_PAD*CH
    float*  zmixP  = uvP + (size_t)CN_PAD * CH;

    cudaFuncSetAttribute(mma_gemm<false, 2, false>, cudaFuncAttributeMaxDynamicSharedMemorySize, SMEM_MMA);
    cudaFuncSetAttribute(mma_gemm<false, 2, true>,  cudaFuncAttributeMaxDynamicSharedMemorySize, SMEM_MMA);
    cudaFuncSetAttribute(mma_gemm<false, 3, false>, cudaFuncAttributeMaxDynamicSharedMemorySize, SMEM_MMA);
    cudaFuncSetAttribute(mma_gemm<true, 3, false>,  cudaFuncAttributeMaxDynamicSharedMemorySize, SMEM_MMA);

    // 0) weight prep + fused-logit weights + init + CSR build + input converts
    transpose_split<<<dim3(CH / 32, CD / 32), dim3(32, 8)>>>(We1, CH, 0,   wuvhi, wuvlo, 0,  CD);
    transpose_split<<<dim3(CH / 32, CD / 32), dim3(32, 8)>>>(We1, CH, 640, wuvhi, wuvlo, CH, CD);
    transpose_split<<<dim3(CH / 32, CS / 32), dim3(32, 8)>>>(We1, CH, 512, wmhi,  wmlo,  0,  CS);
    transpose_split<<<dim3(CD / 32, CH / 32), dim3(32, 8)>>>(We2, CD, 0,   w2hi,  w2lo,  0,  CH);
    transpose_split<<<dim3(CD / 32, CH / 32), dim3(32, 8)>>>(Wn,  CD, 0,   wnhi,  wnlo,  0,  CH);
    transpose_split<<<dim3(CD / 32, K1 / 32), dim3(32, 8)>>>(Wp1, CD, 0,   wphi,  wplo,  0,  K1);
    w2a_kernel<<<CH / 8, 256>>>(We2, Wa, w2aP);
    ba2_kernel<<<1, 256>>>(be2, Wa, ba, ba2P);
    init_kernel<<<(CN + 255) / 256, 256>>>(mP, denP, degP);
    count_kernel<<<(CE + 255) / 256, 256>>>(dst, degP);
    scan_kernel<<<1, 1024>>>(degP, offsP, cursorP);
    fill_kernel<<<(CE + 255) / 256, 256>>>(dst, cursorP, elistP);
    cvt_nf<<<CN_PAD, 128>>>(n_f, nfhi);
    cvt_sf<<<(CE * CS / 4) / 256, 256>>>(s_f, sfhi);

    // 1a) [U|V] = n_f @ [Wtop Wbot]           [N, 2048]   (2-pass)
    mma_gemm<false, 2, false><<<dim3(2 * CH / 256, CN_PAD / 128), 256, SMEM_MMA>>>(
        CN, 2 * CH, CD, nfhi, nullptr, wuvhi, wuvlo, zeroP, nullptr, nullptr, uvP);

    // 1b) S = s_f @ Wmid + be1                [E, 1024]   (2-pass)
    mma_gemm<false, 2, false><<<dim3(CH / 256, CE / 128), 256, SMEM_MMA>>>(
        CE, CH, CS, sfhi, nullptr, wmhi, wmlo, be1, nullptr, nullptr, sP);

    // 1c) hidden fp16 + logit a + segment max  (overwrites sf)
    fuse_hidden<<<CE, 256>>>(uvP, sP, w2aP, ba2P, src, dst, hidHi, aP, mP);

    // 2) softmax denominator
    edge_exp_kernel<<<(CE + 255) / 256, 256>>>(aP, dst, mP, exP, denP);

    // 3) CSR segment reduce: hbar16[n] = sum alpha*hidden, zf[n] = sum alpha*nf[src]
    node_reduce<<<CN, 256>>>(offsP, elistP, src, exP, denP, hidHi, n_f, hbar16, zfP);

    // 4) zmix = hbar @ We2 + gate*be2 + zf    [N, 512]    (2-pass)
    mma_gemm<false, 2, true><<<dim3(CD / 256, CN_PAD / 128), 256, SMEM_MMA>>>(
        CN, CD, CH, hbar16, nullptr, w2hi, w2lo, be2, zfP, denP, zmixP);

    // 5) new_n = concat(n_f, zmix) @ Wn + bn  [N, 512]    (3-pass)
    split_node<<<CN_PAD, 256>>>(n_f, zmixP, anhi, anlo);
    mma_gemm<false, 3, false><<<dim3(CD / 256, CN_PAD / 128), 256, SMEM_MMA>>>(
        CN, CD, CH, anhi, anlo, wnhi, wnlo, bn, nullptr, nullptr, newnP);

    // 6) ph = relu(concat(new_n[sp], s_f[pe], new_n[dp]) @ Wp1 + bp1)  (3-pass)
    split_pred<<<CP_PAD, 288>>>(newnP, s_f, src, dst, pidx, aphi, aplo);
    mma_gemm<true, 3, false><<<dim3(CD / 256, CP_PAD / 128), 256, SMEM_MMA>>>(
        CP, CD, K1, aphi, aplo, wphi, wplo, bp1, nullptr, nullptr, phP);

    // 7) pred = ph @ Wp2 + bp2
    pred_kernel<<<CP / 8, 256>>>(phP, Wp2, bp2, out);
}